// round 2
// baseline (speedup 1.0000x reference)
#include <cuda_runtime.h>
#include <cuda_bf16.h>
#include <math.h>

// ---------------- problem constants ----------------
#define BATCH 8
#define NS 512
#define NT 512
#define NSRC 4096
#define NTRG 4096
#define NEDGE 32768
#define EMBED 128
#define ORI 1024
#define CONV_IN 256
#define FINAL_IN 1408          // 1024 + 3*128
#define KK 25
#define YW 3200                // KK * EMBED
#define CHUNK 32
#define NCHUNK 1024            // NEDGE / CHUNK

// ---------------- device scratch (statics only; no allocs) ----------------
__device__ float g_feat_s[NSRC * FINAL_IN];
__device__ float g_feat_t[NTRG * FINAL_IN];
__device__ float g_extra_s[NSRC * 40];
__device__ float g_extra_t[NTRG * 40];
__device__ float g_xin_s[NSRC * EMBED];
__device__ float g_xin_t[NTRG * EMBED];
__device__ float g_msg_s[NSRC * EMBED];
__device__ float g_msg_t[NTRG * EMBED];
__device__ float g_cat_s[NSRC * CONV_IN];
__device__ float g_cat_t[NTRG * CONV_IN];
__device__ float g_Y[NSRC * YW];                 // 52 MB, reused s then t
__device__ float g_rootb[NSRC * EMBED];
__device__ float g_hs[NSRC * EMBED];
__device__ float g_ht[NTRG * EMBED];
__device__ float g_Wr[3 * CONV_IN * YW];         // rearranged conv_w per layer: [256][3200]
__device__ float g_rowsum[NSRC];
__device__ float g_colsum[NTRG];
__device__ int   g_cnt[4096 * NCHUNK];           // [dst][chunk]
__device__ int   g_tot[4096];
__device__ int   g_off_s[4097];
__device__ int   g_eid_s[NEDGE];
__device__ int   g_off_t[4097];
__device__ int   g_eid_t[NEDGE];

// ---------------- generic fp32 GEMM: C = A(MxK) * B(KxN) (+bias) ----------------
// BM=128, BN=64, BK=16, 256 threads, 8x4 per thread. M%128==0, N%64==0 required.
template <bool TA, bool TB, bool ACC>
__global__ void gemm_k(const float* __restrict__ A, int lda, long long sA,
                       const float* __restrict__ B, int ldb, long long sB,
                       float* __restrict__ C, int ldc, long long sC,
                       const float* __restrict__ bias,
                       int M, int N, int K)
{
    const int bz = blockIdx.z;
    A += bz * sA; B += bz * sB; C += bz * sC;
    __shared__ float As[16][132];
    __shared__ float Bs[16][68];
    const int tid = threadIdx.x;
    const int m0 = blockIdx.y * 128, n0 = blockIdx.x * 64;
    const int tx = tid & 15, ty = tid >> 4;   // tx: n (4 each), ty: m (8 each)
    float acc[8][4];
#pragma unroll
    for (int i = 0; i < 8; i++)
#pragma unroll
        for (int j = 0; j < 4; j++) acc[i][j] = 0.f;

    for (int k0 = 0; k0 < K; k0 += 16) {
        // ---- load A tile -> As[k][m]
        if (!TA) {
            int c = tid & 15;        // k
            int r = tid >> 4;        // m group
#pragma unroll
            for (int i = 0; i < 8; i++) {
                int m = r + i * 16;
                float v = 0.f;
                if (k0 + c < K) v = A[(long long)(m0 + m) * lda + k0 + c];
                As[c][m] = v;
            }
        } else {
            int c = tid & 127;       // m
            int r = tid >> 7;        // k base (0..1)
#pragma unroll
            for (int i = 0; i < 8; i++) {
                int k = r + i * 2;
                float v = 0.f;
                if (k0 + k < K) v = A[(long long)(k0 + k) * lda + m0 + c];
                As[k][c] = v;
            }
        }
        // ---- load B tile -> Bs[k][n]
        if (!TB) {
            int c = tid & 63;        // n
            int r = tid >> 6;        // k base (0..3)
#pragma unroll
            for (int i = 0; i < 4; i++) {
                int k = r + i * 4;
                float v = 0.f;
                if (k0 + k < K) v = B[(long long)(k0 + k) * ldb + n0 + c];
                Bs[k][c] = v;
            }
        } else {
            int c = tid & 15;        // k
            int r = tid >> 4;        // n group
#pragma unroll
            for (int i = 0; i < 4; i++) {
                int n = r + i * 16;
                float v = 0.f;
                if (k0 + c < K) v = B[(long long)(n0 + n) * ldb + k0 + c];
                Bs[c][n] = v;
            }
        }
        __syncthreads();
#pragma unroll
        for (int k = 0; k < 16; k++) {
            float a[8], b[4];
#pragma unroll
            for (int i = 0; i < 8; i++) a[i] = As[k][ty * 8 + i];
#pragma unroll
            for (int j = 0; j < 4; j++) b[j] = Bs[k][tx * 4 + j];
#pragma unroll
            for (int i = 0; i < 8; i++)
#pragma unroll
                for (int j = 0; j < 4; j++) acc[i][j] += a[i] * b[j];
        }
        __syncthreads();
    }
#pragma unroll
    for (int i = 0; i < 8; i++) {
        int m = m0 + ty * 8 + i;
#pragma unroll
        for (int j = 0; j < 4; j++) {
            int n = n0 + tx * 4 + j;
            float v = acc[i][j];
            if (bias) v += bias[n];
            long long off = (long long)m * ldc + n;
            if (ACC) C[off] += v; else C[off] = v;
        }
    }
}

// ---------------- misc kernels ----------------
__global__ void k_rowsum(const float* __restrict__ Xt, float* __restrict__ rs) {
    int n = blockIdx.x;
    const float* row = Xt + (long long)n * NT;
    __shared__ float sm[256];
    float s = row[threadIdx.x] + row[threadIdx.x + 256];
    sm[threadIdx.x] = s; __syncthreads();
    for (int st = 128; st > 0; st >>= 1) {
        if (threadIdx.x < st) sm[threadIdx.x] += sm[threadIdx.x + st];
        __syncthreads();
    }
    if (threadIdx.x == 0) rs[n] = sm[0];
}

__global__ void k_colsum(const float* __restrict__ Xt, float* __restrict__ cs) {
    int b = blockIdx.x, t = threadIdx.x;       // 512 threads
    float s = 0.f;
    const float* base = Xt + (long long)b * NS * NT + t;
    for (int srow = 0; srow < NS; srow++) s += base[srow * NT];
    cs[b * NT + t] = s;
}

__global__ void k_extra(const float* __restrict__ sums, const float* __restrict__ tvec,
                        float* __restrict__ extra) {
    int n = blockIdx.x * blockDim.x + threadIdx.x;
    if (n >= NSRC) return;
    float x = sums[n] * 0.1f;
    float tb = tvec[n >> 9];
    const float c = -1.0233711524418064f;      // -ln(10000)/9
#pragma unroll
    for (int i = 0; i < 10; i++) {
        float f = expf(c * (float)i);
        float ax = x * f, at = tb * f;
        extra[n * 40 + i]      = sinf(ax);
        extra[n * 40 + 10 + i] = cosf(ax);
        extra[n * 40 + 20 + i] = sinf(at);
        extra[n * 40 + 30 + i] = cosf(at);
    }
}

__global__ void k_copyx(const float* __restrict__ x, float* __restrict__ feat) {
    int n = blockIdx.x;
    feat[(long long)n * FINAL_IN + threadIdx.x] = x[(long long)n * ORI + threadIdx.x];
}

__global__ void k_wrearr(const float* __restrict__ cw, float* __restrict__ Wr) {
    int idx = blockIdx.x * blockDim.x + threadIdx.x;
    if (idx >= 3 * KK * CONV_IN * EMBED) return;
    int d = idx & 127;
    int r = idx >> 7;
    int k = r & 255; r >>= 8;
    int kk = r % KK; int l = r / KK;
    Wr[((long long)l * CONV_IN + k) * YW + kk * EMBED + d] = cw[idx];
}

__global__ void k_cat(const float* __restrict__ xin, const float* __restrict__ msg,
                      float* __restrict__ cat) {
    int n = blockIdx.x, d = threadIdx.x;       // 256 threads
    float v;
    if (d < EMBED) v = xin[n * EMBED + d];
    else           v = xin[n * EMBED + d - EMBED] - msg[n * EMBED + d - EMBED];
    cat[n * CONV_IN + d] = v;
}

// ----- stable CSR build -----
__global__ void k_count(const int* __restrict__ ei, int* __restrict__ cnt) {
    int e = blockIdx.x * 256 + threadIdx.x;
    int d = ei[NEDGE + e];
    atomicAdd(&cnt[d * NCHUNK + (e >> 5)], 1);
}
__global__ void k_colscan(int* __restrict__ cnt, int* __restrict__ tot) {
    int d = blockIdx.x * 256 + threadIdx.x;
    if (d >= 4096) return;
    int run = 0;
    int* row = cnt + d * NCHUNK;
    for (int c = 0; c < NCHUNK; c++) { int v = row[c]; row[c] = run; run += v; }
    tot[d] = run;
}
__global__ void k_scan(const int* __restrict__ tot, int* __restrict__ off) {
    __shared__ int s[1024];
    int tid = threadIdx.x;
    int v[4]; int sum = 0;
#pragma unroll
    for (int i = 0; i < 4; i++) { v[i] = tot[tid * 4 + i]; sum += v[i]; }
    s[tid] = sum; __syncthreads();
    for (int d = 1; d < 1024; d <<= 1) {
        int x = (tid >= d) ? s[tid - d] : 0;
        __syncthreads();
        s[tid] += x;
        __syncthreads();
    }
    int run = (tid == 0) ? 0 : s[tid - 1];
#pragma unroll
    for (int i = 0; i < 4; i++) { off[tid * 4 + i] = run; run += v[i]; }
    if (tid == 1023) off[4096] = run;
}
__global__ void k_place(const int* __restrict__ ei, const int* __restrict__ off,
                        int* __restrict__ cnt, int* __restrict__ eid) {
    int c = blockIdx.x * 256 + threadIdx.x;
    if (c >= NCHUNK) return;
    for (int j = 0; j < CHUNK; j++) {
        int e = c * CHUNK + j;
        int d = ei[NEDGE + e];
        int r = cnt[d * NCHUNK + c];
        cnt[d * NCHUNK + c] = r + 1;
        eid[off[d] + r] = e;
    }
}

// ----- spline gather-aggregate + mean + root + bias + tanh -----
__global__ void k_spline_agg(const float* __restrict__ Y, const float* __restrict__ rootb,
                             const int* __restrict__ off, const int* __restrict__ eid,
                             const int* __restrict__ ei, const float* __restrict__ ea,
                             float* __restrict__ out /* feat + col offset */) {
    int n = blockIdx.x, d = threadIdx.x;       // 128 threads
    int beg = off[n], end = off[n + 1];
    float acc = 0.f;
    for (int j = beg; j < end; j++) {
        int e = eid[j];
        int src = ei[e];
        float v0 = ea[e * 2] * 4.f, v1 = ea[e * 2 + 1] * 4.f;
        float l0 = floorf(v0), l1 = floorf(v1);
        float f0 = v0 - l0, f1 = v1 - l1;
        int i0 = (int)l0, i1 = (int)l1;
        const float* Ys = Y + (long long)src * YW;
#pragma unroll
        for (int s1 = 0; s1 < 2; s1++) {
#pragma unroll
            for (int s0 = 0; s0 < 2; s0++) {
                int a0 = min(max(i0 + s0, 0), 4);
                int a1 = min(max(i1 + s1, 0), 4);
                float w = (s0 ? f0 : 1.f - f0) * (s1 ? f1 : 1.f - f1);
                acc += w * Ys[(a0 + 5 * a1) * EMBED + d];
            }
        }
    }
    float deg = (float)(end - beg);
    acc = acc / fmaxf(deg, 1.f);
    float v = acc + rootb[n * EMBED + d];
    out[(long long)n * FINAL_IN + d] = tanhf(v);
}

__global__ void k_softmax(float* __restrict__ out) {
    int r = blockIdx.x;
    float* row = out + (long long)r * NT;
    __shared__ float sm[256];
    int tid = threadIdx.x;
    float a = row[tid], b = row[tid + 256];
    sm[tid] = fmaxf(a, b); __syncthreads();
    for (int s = 128; s > 0; s >>= 1) {
        if (tid < s) sm[tid] = fmaxf(sm[tid], sm[tid + s]);
        __syncthreads();
    }
    float mx = sm[0]; __syncthreads();
    float ea = expf(a - mx), eb = expf(b - mx);
    sm[tid] = ea + eb; __syncthreads();
    for (int s = 128; s > 0; s >>= 1) {
        if (tid < s) sm[tid] += sm[tid + s];
        __syncthreads();
    }
    float inv = 1.f / sm[0];
    row[tid] = ea * inv;
    row[tid + 256] = eb * inv;
}

// ---------------- host orchestration ----------------
static void build_csr(const int* ei, int* off, int* eid, int* cnt, int* tot) {
    cudaMemsetAsync(cnt, 0, 4096 * NCHUNK * sizeof(int));
    k_count<<<NEDGE / 256, 256>>>(ei, cnt);
    k_colscan<<<16, 256>>>(cnt, tot);
    k_scan<<<1, 1024>>>(tot, off);
    k_place<<<4, 256>>>(ei, off, cnt, eid);
}

extern "C" void kernel_launch(void* const* d_in, const int* in_sizes, int n_in,
                              void* d_out, int out_size) {
    const float* t_in     = (const float*)d_in[0];
    const float* Xt       = (const float*)d_in[1];
    const float* x_s      = (const float*)d_in[2];
    const float* x_t      = (const float*)d_in[3];
    const float* ea_s     = (const float*)d_in[4];
    const float* ea_t     = (const float*)d_in[5];
    const float* lin0_w   = (const float*)d_in[6];
    const float* lin0_b   = (const float*)d_in[7];
    const float* lin_w    = (const float*)d_in[8];
    const float* lin_b    = (const float*)d_in[9];
    const float* conv_w   = (const float*)d_in[10];
    const float* conv_root= (const float*)d_in[11];
    const float* conv_bias= (const float*)d_in[12];
    const float* final_w  = (const float*)d_in[13];
    const float* final_b  = (const float*)d_in[14];
    const int*   ei_s     = (const int*)d_in[15];
    const int*   ei_t     = (const int*)d_in[16];
    float* out = (float*)d_out;

    float *feat_s, *feat_t, *extra_s, *extra_t, *xin_s, *xin_t, *msg_s, *msg_t;
    float *cat_s, *cat_t, *Y, *rootb, *hs, *ht, *Wr, *rowsum, *colsum;
    int *cnt, *tot, *off_s, *eid_s, *off_t, *eid_t;
    cudaGetSymbolAddress((void**)&feat_s, g_feat_s);
    cudaGetSymbolAddress((void**)&feat_t, g_feat_t);
    cudaGetSymbolAddress((void**)&extra_s, g_extra_s);
    cudaGetSymbolAddress((void**)&extra_t, g_extra_t);
    cudaGetSymbolAddress((void**)&xin_s, g_xin_s);
    cudaGetSymbolAddress((void**)&xin_t, g_xin_t);
    cudaGetSymbolAddress((void**)&msg_s, g_msg_s);
    cudaGetSymbolAddress((void**)&msg_t, g_msg_t);
    cudaGetSymbolAddress((void**)&cat_s, g_cat_s);
    cudaGetSymbolAddress((void**)&cat_t, g_cat_t);
    cudaGetSymbolAddress((void**)&Y, g_Y);
    cudaGetSymbolAddress((void**)&rootb, g_rootb);
    cudaGetSymbolAddress((void**)&hs, g_hs);
    cudaGetSymbolAddress((void**)&ht, g_ht);
    cudaGetSymbolAddress((void**)&Wr, g_Wr);
    cudaGetSymbolAddress((void**)&rowsum, g_rowsum);
    cudaGetSymbolAddress((void**)&colsum, g_colsum);
    cudaGetSymbolAddress((void**)&cnt, g_cnt);
    cudaGetSymbolAddress((void**)&tot, g_tot);
    cudaGetSymbolAddress((void**)&off_s, g_off_s);
    cudaGetSymbolAddress((void**)&eid_s, g_eid_s);
    cudaGetSymbolAddress((void**)&off_t, g_off_t);
    cudaGetSymbolAddress((void**)&eid_t, g_eid_t);

    // ---- prep ----
    k_rowsum<<<NSRC, 256>>>(Xt, rowsum);
    k_colsum<<<BATCH, 512>>>(Xt, colsum);
    k_extra<<<16, 256>>>(rowsum, t_in, extra_s);
    k_extra<<<16, 256>>>(colsum, t_in, extra_t);
    k_copyx<<<NSRC, 1024>>>(x_s, feat_s);
    k_copyx<<<NTRG, 1024>>>(x_t, feat_t);
    k_wrearr<<<(3 * KK * CONV_IN * EMBED + 255) / 256, 256>>>(conv_w, Wr);
    build_csr(ei_s, off_s, eid_s, cnt, tot);
    build_csr(ei_t, off_t, eid_t, cnt, tot);

    for (int l = 0; l < 3; l++) {
        const float* W    = (l == 0) ? lin0_w : lin_w + (long long)(l - 1) * 168 * EMBED;
        const float* bws  = (l == 0) ? lin0_b : lin_b + (l - 1) * EMBED;
        int K1 = (l == 0) ? ORI : EMBED;
        const float* As = (l == 0) ? feat_s : feat_s + ORI + (l - 1) * EMBED;
        const float* At = (l == 0) ? feat_t : feat_t + ORI + (l - 1) * EMBED;

        // xin = prev @ W_top + bias ; xin += extra @ W_bot
        {
            dim3 g(EMBED / 64, NSRC / 128, 1);
            gemm_k<false,false,false><<<g, 256>>>(As, FINAL_IN, 0, W, EMBED, 0,
                                                  xin_s, EMBED, 0, bws, NSRC, EMBED, K1);
            gemm_k<false,false,true><<<g, 256>>>(extra_s, 40, 0, W + (long long)K1 * EMBED, EMBED, 0,
                                                 xin_s, EMBED, 0, nullptr, NSRC, EMBED, 40);
            gemm_k<false,false,false><<<g, 256>>>(At, FINAL_IN, 0, W, EMBED, 0,
                                                  xin_t, EMBED, 0, bws, NTRG, EMBED, K1);
            gemm_k<false,false,true><<<g, 256>>>(extra_t, 40, 0, W + (long long)K1 * EMBED, EMBED, 0,
                                                 xin_t, EMBED, 0, nullptr, NTRG, EMBED, 40);
        }
        // tgt_msg = Xt @ xp_t ; src_msg = Xt^T @ xp_s   (batched over B)
        {
            dim3 g(EMBED / 64, NS / 128, BATCH);
            gemm_k<false,false,false><<<g, 256>>>(Xt, NT, (long long)NS * NT,
                                                  xin_t, EMBED, (long long)NT * EMBED,
                                                  msg_s, EMBED, (long long)NS * EMBED,
                                                  nullptr, NS, EMBED, NT);
            gemm_k<true,false,false><<<g, 256>>>(Xt, NT, (long long)NS * NT,
                                                 xin_s, EMBED, (long long)NS * EMBED,
                                                 msg_t, EMBED, (long long)NT * EMBED,
                                                 nullptr, NT, EMBED, NS);
        }
        k_cat<<<NSRC, 256>>>(xin_s, msg_s, cat_s);
        k_cat<<<NTRG, 256>>>(xin_t, msg_t, cat_t);

        const float* Wl = Wr + (long long)l * CONV_IN * YW;
        const float* rootl = conv_root + (long long)l * CONV_IN * EMBED;
        const float* biasl = conv_bias + l * EMBED;

        // side S
        {
            dim3 gy(YW / 64, NSRC / 128, 1);
            gemm_k<false,false,false><<<gy, 256>>>(cat_s, CONV_IN, 0, Wl, YW, 0,
                                                   Y, YW, 0, nullptr, NSRC, YW, CONV_IN);
            dim3 gr(EMBED / 64, NSRC / 128, 1);
            gemm_k<false,false,false><<<gr, 256>>>(cat_s, CONV_IN, 0, rootl, EMBED, 0,
                                                   rootb, EMBED, 0, biasl, NSRC, EMBED, CONV_IN);
            k_spline_agg<<<NSRC, 128>>>(Y, rootb, off_s, eid_s, ei_s, ea_s,
                                        feat_s + ORI + l * EMBED);
        }
        // side T
        {
            dim3 gy(YW / 64, NTRG / 128, 1);
            gemm_k<false,false,false><<<gy, 256>>>(cat_t, CONV_IN, 0, Wl, YW, 0,
                                                   Y, YW, 0, nullptr, NTRG, YW, CONV_IN);
            dim3 gr(EMBED / 64, NTRG / 128, 1);
            gemm_k<false,false,false><<<gr, 256>>>(cat_t, CONV_IN, 0, rootl, EMBED, 0,
                                                   rootb, EMBED, 0, biasl, NTRG, EMBED, CONV_IN);
            k_spline_agg<<<NTRG, 128>>>(Y, rootb, off_t, eid_t, ei_t, ea_t,
                                        feat_t + ORI + l * EMBED);
        }
    }

    // final projection
    {
        dim3 g(EMBED / 64, NSRC / 128, 1);
        gemm_k<false,false,false><<<g, 256>>>(feat_s, FINAL_IN, 0, final_w, EMBED, 0,
                                              hs, EMBED, 0, final_b, NSRC, EMBED, FINAL_IN);
        gemm_k<false,false,false><<<g, 256>>>(feat_t, FINAL_IN, 0, final_w, EMBED, 0,
                                              ht, EMBED, 0, final_b, NTRG, EMBED, FINAL_IN);
    }
    // sim = h_s @ h_t^T (batched), then row softmax in place on d_out
    {
        dim3 g(NT / 64, NS / 128, BATCH);
        gemm_k<false,true,false><<<g, 256>>>(hs, EMBED, (long long)NS * EMBED,
                                             ht, EMBED, (long long)NT * EMBED,
                                             out, NT, (long long)NS * NT,
                                             nullptr, NS, NT, EMBED);
    }
    k_softmax<<<NSRC, 256>>>(out);
}

// round 4
// speedup vs baseline: 1.8710x; 1.8710x over previous
#include <cuda_runtime.h>
#include <cuda_bf16.h>
#include <math.h>
#include <stdint.h>

// ---------------- problem constants ----------------
#define BATCH 8
#define NS 512
#define NT 512
#define NSRC 4096
#define NTOT 8192
#define NEDGE 32768
#define EMBED 128
#define ORI 1024
#define CONV_IN 256
#define FINAL_IN 1408
#define KK 25
#define YW 3200
#define CHUNK 32
#define NCHUNK 1024
#define K0PAD 1088   // 1064 -> 1088
#define KLPAD 192    // 168 -> 192

typedef __nv_bfloat16 bf16;

// ---------------- device scratch ----------------
__device__ __align__(16) bf16 g_xcat_h[NTOT * K0PAD];
__device__ __align__(16) bf16 g_xcat_l[NTOT * K0PAD];
__device__ __align__(16) bf16 g_Xh[BATCH * NS * NT];
__device__ __align__(16) bf16 g_Xl[BATCH * NS * NT];
__device__ __align__(16) bf16 g_XTh[BATCH * NS * NT];
__device__ __align__(16) bf16 g_XTl[BATCH * NS * NT];
__device__ __align__(16) bf16 g_xinT_h[EMBED * NTOT];
__device__ __align__(16) bf16 g_xinT_l[EMBED * NTOT];
__device__ __align__(16) bf16 g_cat_h[NTOT * CONV_IN];
__device__ __align__(16) bf16 g_cat_l[NTOT * CONV_IN];
__device__ __align__(16) bf16 g_feat_h[NTOT * FINAL_IN];
__device__ __align__(16) bf16 g_feat_l[NTOT * FINAL_IN];
__device__ __align__(16) bf16 g_hh[NTOT * EMBED];
__device__ __align__(16) bf16 g_hl[NTOT * EMBED];
__device__ __align__(16) bf16 g_WrT_h[3 * YW * CONV_IN];
__device__ __align__(16) bf16 g_WrT_l[3 * YW * CONV_IN];
__device__ __align__(16) bf16 g_WT0_h[EMBED * K0PAD];
__device__ __align__(16) bf16 g_WT0_l[EMBED * K0PAD];
__device__ __align__(16) bf16 g_WTl_h[2 * EMBED * KLPAD];
__device__ __align__(16) bf16 g_WTl_l[2 * EMBED * KLPAD];
__device__ __align__(16) bf16 g_rtT_h[3 * EMBED * CONV_IN];
__device__ __align__(16) bf16 g_rtT_l[3 * EMBED * CONV_IN];
__device__ __align__(16) bf16 g_fwT_h[EMBED * FINAL_IN];
__device__ __align__(16) bf16 g_fwT_l[EMBED * FINAL_IN];
__device__ float g_xin[NTOT * EMBED];
__device__ float g_msg[NTOT * EMBED];
__device__ float g_rootb[NTOT * EMBED];
__device__ float g_hf[NTOT * EMBED];
__device__ float g_Y[NTOT * YW];
__device__ float g_extra[NTOT * 40];
__device__ float g_sum[NTOT];
__device__ int   g_cnt[4096 * NCHUNK];
__device__ int   g_tot[4096];
__device__ int   g_off_s[4097];
__device__ int   g_eid_s[NEDGE];
__device__ int   g_off_t[4097];
__device__ int   g_eid_t[NEDGE];

// ---------------- helpers ----------------
__device__ __forceinline__ void bsplit(float v, bf16& h, bf16& l) {
    h = __float2bfloat16(v);
    l = __float2bfloat16(v - __bfloat162float(h));
}
__device__ __forceinline__ uint32_t smem_u32(const void* p) {
    uint32_t a;
    asm("{ .reg .u64 t; cvta.to.shared.u64 t, %1; cvt.u32.u64 %0, t; }" : "=r"(a) : "l"(p));
    return a;
}
__device__ __forceinline__ void cp16(uint32_t s, const void* g) {
    asm volatile("cp.async.cg.shared.global [%0], [%1], 16;" :: "r"(s), "l"(g));
}
__device__ __forceinline__ void ldsm4(uint32_t* r, uint32_t a) {
    asm volatile("ldmatrix.sync.aligned.m8n8.x4.shared.b16 {%0,%1,%2,%3}, [%4];"
                 : "=r"(r[0]), "=r"(r[1]), "=r"(r[2]), "=r"(r[3]) : "r"(a));
}
__device__ __forceinline__ void ldsm2(uint32_t* r, uint32_t a) {
    asm volatile("ldmatrix.sync.aligned.m8n8.x2.shared.b16 {%0,%1}, [%2];"
                 : "=r"(r[0]), "=r"(r[1]) : "r"(a));
}
__device__ __forceinline__ void mma16816(float* d, const uint32_t* a, const uint32_t* b) {
    asm volatile("mma.sync.aligned.m16n8k16.row.col.f32.bf16.bf16.f32 "
                 "{%0,%1,%2,%3}, {%4,%5,%6,%7}, {%8,%9}, {%0,%1,%2,%3};"
                 : "+f"(d[0]), "+f"(d[1]), "+f"(d[2]), "+f"(d[3])
                 : "r"(a[0]), "r"(a[1]), "r"(a[2]), "r"(a[3]), "r"(b[0]), "r"(b[1]));
}

// ======================================================================
// bf16 3-term GEMM: C[M,N] = Ah*Bh + Ah*Bl + Al*Bh (+bias), fp32 accum.
// A: [m][k] rows, B: [n][k] rows (pre-split bf16). M,N mult of 128; K mult of 32.
// ======================================================================
#define GSMEM (2 * 4 * 10240)   // 81920

__global__ void __launch_bounds__(256, 2) bgemm(
    const bf16* __restrict__ Ah, const bf16* __restrict__ Al, int lda, long long sA,
    const bf16* __restrict__ Bh, const bf16* __restrict__ Bl, int ldb, long long sB,
    float* __restrict__ C, int ldc, long long sC,
    const float* __restrict__ bias, int K)
{
    extern __shared__ char smem[];
    const uint32_t sb = smem_u32(smem);
    const int tid = threadIdx.x, wid = tid >> 5, lane = tid & 31;
    const int wm = wid & 1, wn = wid >> 1;           // warp: 64m x 32n
    Ah += (long long)blockIdx.z * sA;  Al += (long long)blockIdx.z * sA;
    Bh += (long long)blockIdx.z * sB;  Bl += (long long)blockIdx.z * sB;
    C  += (long long)blockIdx.z * sC;
    const int m0 = blockIdx.y * 128, n0 = blockIdx.x * 128;

    const int nch = K >> 5;
    float acc[4][4][4];
#pragma unroll
    for (int i = 0; i < 4; i++)
#pragma unroll
        for (int j = 0; j < 4; j++)
#pragma unroll
            for (int q = 0; q < 4; q++) acc[i][j][q] = 0.f;

    // staging assignment: 2048 x 16B per chunk, 8 per thread
    // idx = tid + i*256: mat = idx>>9 (0:Ah 1:Al 2:Bh 3:Bl), r=(idx>>2)&127, seg=idx&3
    auto issue = [&](int c, int buf) {
        const int k0 = c << 5;
#pragma unroll
        for (int i = 0; i < 8; i++) {
            int idx = tid + i * 256;
            int mat = idx >> 9, r = (idx >> 2) & 127, seg = idx & 3;
            uint32_t dst = sb + buf * 40960 + mat * 10240 + r * 80 + seg * 16;
            const bf16* src;
            if (mat == 0)      src = Ah + (long long)(m0 + r) * lda + k0 + seg * 8;
            else if (mat == 1) src = Al + (long long)(m0 + r) * lda + k0 + seg * 8;
            else if (mat == 2) src = Bh + (long long)(n0 + r) * ldb + k0 + seg * 8;
            else               src = Bl + (long long)(n0 + r) * ldb + k0 + seg * 8;
            cp16(dst, src);
        }
        asm volatile("cp.async.commit_group;");
    };

    issue(0, 0);
    int cur = 0;
    for (int c = 0; c < nch; c++) {
        if (c + 1 < nch) issue(c + 1, cur ^ 1);
        if (c + 1 < nch) asm volatile("cp.async.wait_group 1;");
        else             asm volatile("cp.async.wait_group 0;");
        __syncthreads();

        const uint32_t base = sb + cur * 40960;
        const uint32_t aRow = (uint32_t)(wm * 64) + (lane & 15);
        const uint32_t aKH  = (lane >> 4) * 16;
        const uint32_t bRow = (uint32_t)(wn * 32) + (lane & 7);
        const uint32_t bKH  = ((lane >> 3) & 1) * 16;
#pragma unroll
        for (int s = 0; s < 2; s++) {
            uint32_t a[4][4], bq[4][2];
#pragma unroll
            for (int mt = 0; mt < 4; mt++)
                ldsm4(a[mt], base + (aRow + mt * 16) * 80 + s * 32 + aKH);
#pragma unroll
            for (int nt = 0; nt < 4; nt++)
                ldsm2(bq[nt], base + 20480 + (bRow + nt * 8) * 80 + s * 32 + bKH);
#pragma unroll
            for (int mt = 0; mt < 4; mt++)
#pragma unroll
                for (int nt = 0; nt < 4; nt++) mma16816(acc[mt][nt], a[mt], bq[nt]);
            // Bl
#pragma unroll
            for (int nt = 0; nt < 4; nt++)
                ldsm2(bq[nt], base + 30720 + (bRow + nt * 8) * 80 + s * 32 + bKH);
#pragma unroll
            for (int mt = 0; mt < 4; mt++)
#pragma unroll
                for (int nt = 0; nt < 4; nt++) mma16816(acc[mt][nt], a[mt], bq[nt]);
            // Al (overwrite a), with Bh reloaded
#pragma unroll
            for (int nt = 0; nt < 4; nt++)
                ldsm2(bq[nt], base + 20480 + (bRow + nt * 8) * 80 + s * 32 + bKH);
#pragma unroll
            for (int mt = 0; mt < 4; mt++)
                ldsm4(a[mt], base + 10240 + (aRow + mt * 16) * 80 + s * 32 + aKH);
#pragma unroll
            for (int mt = 0; mt < 4; mt++)
#pragma unroll
                for (int nt = 0; nt < 4; nt++) mma16816(acc[mt][nt], a[mt], bq[nt]);
        }
        __syncthreads();
        cur ^= 1;
    }

    // epilogue
    const int rbase = m0 + wm * 64 + (lane >> 2);
    const int cbase = n0 + wn * 32 + 2 * (lane & 3);
#pragma unroll
    for (int mt = 0; mt < 4; mt++) {
#pragma unroll
        for (int nt = 0; nt < 4; nt++) {
            int r = rbase + mt * 16, cc = cbase + nt * 8;
            float b0 = 0.f, b1 = 0.f;
            if (bias) { b0 = bias[cc]; b1 = bias[cc + 1]; }
            float2 v0 = make_float2(acc[mt][nt][0] + b0, acc[mt][nt][1] + b1);
            float2 v1 = make_float2(acc[mt][nt][2] + b0, acc[mt][nt][3] + b1);
            *(float2*)(C + (long long)r * ldc + cc) = v0;
            *(float2*)(C + (long long)(r + 8) * ldc + cc) = v1;
        }
    }
}

// ---------------- transpose + split: in fp32 [R][C] -> out bf16 [C][Rpad] ----------------
__global__ void k_convT(const float* __restrict__ in, int R, int C, int ldin, long long sIn,
                        bf16* __restrict__ oh, bf16* __restrict__ ol, int Rpad, long long sOut) {
    __shared__ float t[32][33];
    in += (long long)blockIdx.z * sIn;
    oh += (long long)blockIdx.z * sOut;
    ol += (long long)blockIdx.z * sOut;
    int r0 = blockIdx.y * 32, c0 = blockIdx.x * 32;
    for (int i = threadIdx.y; i < 32; i += 8) {
        int r = r0 + i, c = c0 + threadIdx.x;
        t[i][threadIdx.x] = (r < R && c < C) ? in[(long long)r * ldin + c] : 0.f;
    }
    __syncthreads();
    for (int i = threadIdx.y; i < 32; i += 8) {
        int c = c0 + i, r = r0 + threadIdx.x;
        if (c < C && r < Rpad) {
            bf16 h, l; bsplit(t[threadIdx.x][i], h, l);
            oh[(long long)c * Rpad + r] = h;
            ol[(long long)c * Rpad + r] = l;
        }
    }
}

// straight split
__global__ void k_convS(const float* __restrict__ in, bf16* __restrict__ oh,
                        bf16* __restrict__ ol, int n) {
    int i = blockIdx.x * 256 + threadIdx.x;
    if (i >= n) return;
    bf16 h, l; bsplit(in[i], h, l);
    oh[i] = h; ol[i] = l;
}

// ---------------- misc kernels ----------------
__global__ void k_rowsum(const float* __restrict__ Xt, float* __restrict__ rs) {
    int n = blockIdx.x;
    const float* row = Xt + (long long)n * NT;
    __shared__ float sm[256];
    float s = row[threadIdx.x] + row[threadIdx.x + 256];
    sm[threadIdx.x] = s; __syncthreads();
    for (int st = 128; st > 0; st >>= 1) {
        if (threadIdx.x < st) sm[threadIdx.x] += sm[threadIdx.x + st];
        __syncthreads();
    }
    if (threadIdx.x == 0) rs[n] = sm[0];
}
__global__ void k_colsum(const float* __restrict__ Xt, float* __restrict__ cs) {
    int b = blockIdx.x, t = threadIdx.x;
    float s = 0.f;
    const float* base = Xt + (long long)b * NS * NT + t;
    for (int srow = 0; srow < NS; srow++) s += base[srow * NT];
    cs[b * NT + t] = s;
}
__global__ void k_extra(const float* __restrict__ sums, const float* __restrict__ tvec,
                        float* __restrict__ extra) {
    int n = blockIdx.x * blockDim.x + threadIdx.x;
    if (n >= NTOT) return;
    float x = sums[n] * 0.1f;
    float tb = tvec[(n >> 9) & 7];
    const float c = -1.0233711524418064f;
#pragma unroll
    for (int i = 0; i < 10; i++) {
        float f = expf(c * (float)i);
        float ax = x * f, at = tb * f;
        extra[n * 40 + i]      = sinf(ax);
        extra[n * 40 + 10 + i] = cosf(ax);
        extra[n * 40 + 20 + i] = sinf(at);
        extra[n * 40 + 30 + i] = cosf(at);
    }
}
__global__ void k_copyx(const float* __restrict__ xs, const float* __restrict__ xt,
                        bf16* __restrict__ fh, bf16* __restrict__ fl) {
    int n = blockIdx.x;
    const float* x = (n < NSRC) ? xs + (long long)n * ORI : xt + (long long)(n - NSRC) * ORI;
    for (int c = threadIdx.x; c < ORI; c += 256) {
        bf16 h, l; bsplit(x[c], h, l);
        fh[(long long)n * FINAL_IN + c] = h;
        fl[(long long)n * FINAL_IN + c] = l;
    }
}
__global__ void k_xcat0(const float* __restrict__ xs, const float* __restrict__ xt,
                        const float* __restrict__ extra,
                        bf16* __restrict__ oh, bf16* __restrict__ ol) {
    int n = blockIdx.x;
    const float* x = (n < NSRC) ? xs + (long long)n * ORI : xt + (long long)(n - NSRC) * ORI;
    for (int c = threadIdx.x; c < K0PAD; c += 256) {
        float v = (c < 1024) ? x[c] : ((c < 1064) ? extra[n * 40 + c - 1024] : 0.f);
        bf16 h, l; bsplit(v, h, l);
        oh[(long long)n * K0PAD + c] = h;
        ol[(long long)n * K0PAD + c] = l;
    }
}
__global__ void k_xcatL(const bf16* __restrict__ fh, const bf16* __restrict__ fl,
                        const float* __restrict__ extra,
                        bf16* __restrict__ oh, bf16* __restrict__ ol, int l) {
    int n = blockIdx.x, c = threadIdx.x;   // 192 threads
    bf16 h = __float2bfloat16(0.f), lo = h;
    if (c < 128) {
        long long o = (long long)n * FINAL_IN + ORI + (l - 1) * EMBED + c;
        h = fh[o]; lo = fl[o];
    } else if (c < 168) {
        bsplit(extra[n * 40 + (c - 128)], h, lo);
    }
    oh[(long long)n * KLPAD + c] = h;
    ol[(long long)n * KLPAD + c] = lo;
}
__global__ void k_cat(const float* __restrict__ xin, const float* __restrict__ msg,
                      bf16* __restrict__ oh, bf16* __restrict__ ol) {
    int n = blockIdx.x, d = threadIdx.x;   // 256
    float v;
    if (d < EMBED) v = xin[n * EMBED + d];
    else           v = xin[n * EMBED + d - EMBED] - msg[n * EMBED + d - EMBED];
    bf16 h, l; bsplit(v, h, l);
    oh[(long long)n * CONV_IN + d] = h;
    ol[(long long)n * CONV_IN + d] = l;
}

// ----- stable CSR build -----
__global__ void k_count(const int* __restrict__ ei, int* __restrict__ cnt) {
    int e = blockIdx.x * 256 + threadIdx.x;
    int d = ei[NEDGE + e];
    atomicAdd(&cnt[d * NCHUNK + (e >> 5)], 1);
}
__global__ void k_colscan(int* __restrict__ cnt, int* __restrict__ tot) {
    int d = blockIdx.x * 256 + threadIdx.x;
    if (d >= 4096) return;
    int run = 0;
    int* row = cnt + d * NCHUNK;
    for (int c = 0; c < NCHUNK; c++) { int v = row[c]; row[c] = run; run += v; }
    tot[d] = run;
}
__global__ void k_scan(const int* __restrict__ tot, int* __restrict__ off) {
    __shared__ int s[1024];
    int tid = threadIdx.x;
    int v[4]; int sum = 0;
#pragma unroll
    for (int i = 0; i < 4; i++) { v[i] = tot[tid * 4 + i]; sum += v[i]; }
    s[tid] = sum; __syncthreads();
    for (int d = 1; d < 1024; d <<= 1) {
        int x = (tid >= d) ? s[tid - d] : 0;
        __syncthreads();
        s[tid] += x;
        __syncthreads();
    }
    int run = (tid == 0) ? 0 : s[tid - 1];
#pragma unroll
    for (int i = 0; i < 4; i++) { off[tid * 4 + i] = run; run += v[i]; }
    if (tid == 1023) off[4096] = run;
}
__global__ void k_place(const int* __restrict__ ei, const int* __restrict__ off,
                        int* __restrict__ cnt, int* __restrict__ eid) {
    int c = blockIdx.x * 256 + threadIdx.x;
    if (c >= NCHUNK) return;
    for (int j = 0; j < CHUNK; j++) {
        int e = c * CHUNK + j;
        int d = ei[NEDGE + e];
        int r = cnt[d * NCHUNK + c];
        cnt[d * NCHUNK + c] = r + 1;
        eid[off[d] + r] = e;
    }
}

// ----- spline gather + mean + root + tanh -> feat hi/lo -----
__global__ void k_spline_agg(const float* __restrict__ Y, const float* __restrict__ rootb,
                             const int* __restrict__ off, const int* __restrict__ eid,
                             const int* __restrict__ ei, const float* __restrict__ ea,
                             bf16* __restrict__ oh, bf16* __restrict__ ol) {
    int n = blockIdx.x, d = threadIdx.x;       // 128
    int beg = off[n], end = off[n + 1];
    float acc = 0.f;
    for (int j = beg; j < end; j++) {
        int e = eid[j];
        int src = ei[e];
        float v0 = ea[e * 2] * 4.f, v1 = ea[e * 2 + 1] * 4.f;
        float l0 = floorf(v0), l1 = floorf(v1);
        float f0 = v0 - l0, f1 = v1 - l1;
        int i0 = (int)l0, i1 = (int)l1;
        const float* Ys = Y + (long long)src * YW;
#pragma unroll
        for (int s1 = 0; s1 < 2; s1++) {
#pragma unroll
            for (int s0 = 0; s0 < 2; s0++) {
                int a0 = min(max(i0 + s0, 0), 4);
                int a1 = min(max(i1 + s1, 0), 4);
                float w = (s0 ? f0 : 1.f - f0) * (s1 ? f1 : 1.f - f1);
                acc += w * Ys[(a0 + 5 * a1) * EMBED + d];
            }
        }
    }
    float deg = (float)(end - beg);
    acc = acc / fmaxf(deg, 1.f);
    float v = tanhf(acc + rootb[n * EMBED + d]);
    bf16 h, l; bsplit(v, h, l);
    oh[(long long)n * FINAL_IN + d] = h;
    ol[(long long)n * FINAL_IN + d] = l;
}

__global__ void k_softmax(float* __restrict__ out) {
    int r = blockIdx.x;
    float* row = out + (long long)r * NT;
    __shared__ float sm[256];
    int tid = threadIdx.x;
    float a = row[tid], b = row[tid + 256];
    sm[tid] = fmaxf(a, b); __syncthreads();
    for (int s = 128; s > 0; s >>= 1) {
        if (tid < s) sm[tid] = fmaxf(sm[tid], sm[tid + s]);
        __syncthreads();
    }
    float mx = sm[0]; __syncthreads();
    float ea = expf(a - mx), eb = expf(b - mx);
    sm[tid] = ea + eb; __syncthreads();
    for (int s = 128; s > 0; s >>= 1) {
        if (tid < s) sm[tid] += sm[tid + s];
        __syncthreads();
    }
    float inv = 1.f / sm[0];
    row[tid] = ea * inv;
    row[tid + 256] = eb * inv;
}

// ---------------- host ----------------
static void build_csr(const int* ei, int* off, int* eid, int* cnt, int* tot) {
    cudaMemsetAsync(cnt, 0, 4096 * NCHUNK * sizeof(int));
    k_count<<<NEDGE / 256, 256>>>(ei, cnt);
    k_colscan<<<16, 256>>>(cnt, tot);
    k_scan<<<1, 1024>>>(tot, off);
    k_place<<<4, 256>>>(ei, off, cnt, eid);
}

#define GETSYM(v, s) cudaGetSymbolAddress((void**)&v, s)

extern "C" void kernel_launch(void* const* d_in, const int* in_sizes, int n_in,
                              void* d_out, int out_size) {
    const float* t_in      = (const float*)d_in[0];
    const float* Xt        = (const float*)d_in[1];
    const float* x_s       = (const float*)d_in[2];
    const float* x_t       = (const float*)d_in[3];
    const float* ea_s      = (const float*)d_in[4];
    const float* ea_t      = (const float*)d_in[5];
    const float* lin0_w    = (const float*)d_in[6];
    const float* lin0_b    = (const float*)d_in[7];
    const float* lin_w     = (const float*)d_in[8];
    const float* lin_b     = (const float*)d_in[9];
    const float* conv_w    = (const float*)d_in[10];
    const float* conv_root = (const float*)d_in[11];
    const float* conv_bias = (const float*)d_in[12];
    const float* final_w   = (const float*)d_in[13];
    const float* final_b   = (const float*)d_in[14];
    const int*   ei_s      = (const int*)d_in[15];
    const int*   ei_t      = (const int*)d_in[16];
    float* out = (float*)d_out;

    cudaFuncSetAttribute(bgemm, cudaFuncAttributeMaxDynamicSharedMemorySize, GSMEM);

    bf16 *xcat_h, *xcat_l, *Xh, *Xl, *XTh, *XTl, *xinT_h, *xinT_l, *cat_h, *cat_l;
    bf16 *feat_h, *feat_l, *hh, *hl, *WrT_h, *WrT_l, *WT0_h, *WT0_l, *WTl_h, *WTl_l;
    bf16 *rtT_h, *rtT_l, *fwT_h, *fwT_l;
    float *xin, *msg, *rootb, *hf, *Y, *extra, *sums;
    int *cnt, *tot, *off_s, *eid_s, *off_t, *eid_t;
    GETSYM(xcat_h, g_xcat_h); GETSYM(xcat_l, g_xcat_l);
    GETSYM(Xh, g_Xh); GETSYM(Xl, g_Xl); GETSYM(XTh, g_XTh); GETSYM(XTl, g_XTl);
    GETSYM(xinT_h, g_xinT_h); GETSYM(xinT_l, g_xinT_l);
    GETSYM(cat_h, g_cat_h); GETSYM(cat_l, g_cat_l);
    GETSYM(feat_h, g_feat_h); GETSYM(feat_l, g_feat_l);
    GETSYM(hh, g_hh); GETSYM(hl, g_hl);
    GETSYM(WrT_h, g_WrT_h); GETSYM(WrT_l, g_WrT_l);
    GETSYM(WT0_h, g_WT0_h); GETSYM(WT0_l, g_WT0_l);
    GETSYM(WTl_h, g_WTl_h); GETSYM(WTl_l, g_WTl_l);
    GETSYM(rtT_h, g_rtT_h); GETSYM(rtT_l, g_rtT_l);
    GETSYM(fwT_h, g_fwT_h); GETSYM(fwT_l, g_fwT_l);
    GETSYM(xin, g_xin); GETSYM(msg, g_msg); GETSYM(rootb, g_rootb);
    GETSYM(hf, g_hf); GETSYM(Y, g_Y); GETSYM(extra, g_extra); GETSYM(sums, g_sum);
    GETSYM(cnt, g_cnt); GETSYM(tot, g_tot);
    GETSYM(off_s, g_off_s); GETSYM(eid_s, g_eid_s);
    GETSYM(off_t, g_off_t); GETSYM(eid_t, g_eid_t);

    dim3 tb(32, 8);

    // ---- prep: sums, extra, CSR ----
    k_rowsum<<<NSRC, 256>>>(Xt, sums);
    k_colsum<<<BATCH, 512>>>(Xt, sums + NSRC);
    k_extra<<<32, 256>>>(sums, t_in, extra);
    build_csr(ei_s, off_s, eid_s, cnt, tot);
    build_csr(ei_t, off_t, eid_t, cnt, tot);

    // ---- conversions: Xt straight + per-batch transpose ----
    k_convS<<<(BATCH * NS * NT + 255) / 256, 256>>>(Xt, Xh, Xl, BATCH * NS * NT);
    k_convT<<<dim3(16, 16, BATCH), tb>>>(Xt, NS, NT, NT, (long long)NS * NT,
                                         XTh, XTl, NS, (long long)NS * NT);
    // weights
    k_convT<<<dim3(4, K0PAD / 32, 1), tb>>>(lin0_w, 1064, EMBED, EMBED, 0,
                                            WT0_h, WT0_l, K0PAD, 0);
    k_convT<<<dim3(4, KLPAD / 32, 2), tb>>>(lin_w, 168, EMBED, EMBED, 168 * EMBED,
                                            WTl_h, WTl_l, KLPAD, (long long)EMBED * KLPAD);
    k_convT<<<dim3(4, 8, 75), tb>>>(conv_w, CONV_IN, EMBED, EMBED, (long long)CONV_IN * EMBED,
                                    WrT_h, WrT_l, CONV_IN, (long long)EMBED * CONV_IN);
    k_convT<<<dim3(4, 8, 3), tb>>>(conv_root, CONV_IN, EMBED, EMBED, (long long)CONV_IN * EMBED,
                                   rtT_h, rtT_l, CONV_IN, (long long)EMBED * CONV_IN);
    k_convT<<<dim3(4, FINAL_IN / 32, 1), tb>>>(final_w, FINAL_IN, EMBED, EMBED, 0,
                                               fwT_h, fwT_l, FINAL_IN, 0);
    // feat x-part
    k_copyx<<<NTOT, 256>>>(x_s, x_t, feat_h, feat_l);

    for (int l = 0; l < 3; l++) {
        const float* bws = (l == 0) ? lin0_b : lin_b + (l - 1) * EMBED;
        int Kl; const bf16 *wh, *wl; int ldk;
        if (l == 0) {
            k_xcat0<<<NTOT, 256>>>(x_s, x_t, extra, xcat_h, xcat_l);
            Kl = K0PAD; wh = WT0_h; wl = WT0_l; ldk = K0PAD;
        } else {
            k_xcatL<<<NTOT, 192>>>(feat_h, feat_l, extra, xcat_h, xcat_l, l);
            Kl = KLPAD; wh = WTl_h + (long long)(l - 1) * EMBED * KLPAD;
            wl = WTl_l + (long long)(l - 1) * EMBED * KLPAD; ldk = KLPAD;
        }
        // xin = xcat @ W + b
        bgemm<<<dim3(1, 64, 1), 256, GSMEM>>>(
            xcat_h, xcat_l, ldk, 0, wh, wl, ldk, 0, xin, EMBED, 0, bws, Kl);
        // xinT (fp32 -> transposed split)
        k_convT<<<dim3(4, 256, 1), tb>>>(xin, NTOT, EMBED, EMBED, 0,
                                         xinT_h, xinT_l, NTOT, 0);
        // tgt_msg: A = Xt[b], B = xinT cols (tgt nodes)
        bgemm<<<dim3(1, 4, 8), 256, GSMEM>>>(
            Xh, Xl, NT, (long long)NS * NT,
            xinT_h + NSRC, xinT_l + NSRC, NTOT, NS,
            msg, EMBED, (long long)NS * EMBED, nullptr, NT);
        // src_msg: A = Xt[b]^T, B = xinT cols (src nodes)
        bgemm<<<dim3(1, 4, 8), 256, GSMEM>>>(
            XTh, XTl, NS, (long long)NS * NT,
            xinT_h, xinT_l, NTOT, NS,
            msg + (long long)NSRC * EMBED, EMBED, (long long)NT * EMBED, nullptr, NS);

        k_cat<<<NTOT, 256>>>(xin, msg, cat_h, cat_l);

        // Y = cat @ Wr[l]
        bgemm<<<dim3(YW / 128, 64, 1), 256, GSMEM>>>(
            cat_h, cat_l, CONV_IN, 0,
            WrT_h + (long long)l * YW * CONV_IN, WrT_l + (long long)l * YW * CONV_IN, CONV_IN, 0,
            Y, YW, 0, nullptr, CONV_IN);
        // rootb = cat @ root + bias
        bgemm<<<dim3(1, 64, 1), 256, GSMEM>>>(
            cat_h, cat_l, CONV_IN, 0,
            rtT_h + (long long)l * EMBED * CONV_IN, rtT_l + (long long)l * EMBED * CONV_IN, CONV_IN, 0,
            rootb, EMBED, 0, conv_bias + l * EMBED, CONV_IN);

        k_spline_agg<<<NSRC, 128>>>(Y, rootb, off_s, eid_s, ei_s, ea_s,
                                    feat_h + ORI + l * EMBED, feat_l + ORI + l * EMBED);
        k_spline_agg<<<NSRC, 128>>>(Y + (long long)NSRC * YW, rootb + (long long)NSRC * EMBED,
                                    off_t, eid_t, ei_t, ea_t,
                                    feat_h + (long long)NSRC * FINAL_IN + ORI + l * EMBED,
                                    feat_l + (long long)NSRC * FINAL_IN + ORI + l * EMBED);
    }

    // h = feat @ final_w + final_b
    bgemm<<<dim3(1, 64, 1), 256, GSMEM>>>(
        feat_h, feat_l, FINAL_IN, 0, fwT_h, fwT_l, FINAL_IN, 0,
        hf, EMBED, 0, final_b, FINAL_IN);
    k_convS<<<(NTOT * EMBED + 255) / 256, 256>>>(hf, hh, hl, NTOT * EMBED);

    // sim = h_s @ h_t^T per batch
    bgemm<<<dim3(4, 4, 8), 256, GSMEM>>>(
        hh, hl, EMBED, (long long)NS * EMBED,
        hh + (long long)NSRC * EMBED, hl + (long long)NSRC * EMBED, EMBED, (long long)NT * EMBED,
        out, NT, (long long)NS * NT, nullptr, EMBED);

    k_softmax<<<NSRC, 256>>>(out);
}

// round 5
// speedup vs baseline: 1.9939x; 1.0657x over previous
#include <cuda_runtime.h>
#include <cuda_bf16.h>
#include <math.h>
#include <stdint.h>

// ---------------- problem constants ----------------
#define BATCH 8
#define NS 512
#define NT 512
#define NSRC 4096
#define NTOT 8192
#define NEDGE 32768
#define EMBED 128
#define ORI 1024
#define CONV_IN 256
#define FINAL_IN 1408
#define KK 25
#define YW 3200
#define CHUNK 32
#define NCHUNK 1024
#define K0PAD 1088
#define KLPAD 192

typedef __nv_bfloat16 bf16;

// ---------------- device scratch ----------------
__device__ __align__(16) bf16 g_xcat_h[NTOT * K0PAD];
__device__ __align__(16) bf16 g_xcat_l[NTOT * K0PAD];
__device__ __align__(16) bf16 g_Xh[BATCH * NS * NT];
__device__ __align__(16) bf16 g_Xl[BATCH * NS * NT];
__device__ __align__(16) bf16 g_XTh[BATCH * NS * NT];
__device__ __align__(16) bf16 g_XTl[BATCH * NS * NT];
__device__ __align__(16) bf16 g_xinT_h[EMBED * NTOT];
__device__ __align__(16) bf16 g_xinT_l[EMBED * NTOT];
__device__ __align__(16) bf16 g_cat_h[NTOT * CONV_IN];
__device__ __align__(16) bf16 g_cat_l[NTOT * CONV_IN];
__device__ __align__(16) bf16 g_feat_h[NTOT * FINAL_IN];
__device__ __align__(16) bf16 g_feat_l[NTOT * FINAL_IN];
__device__ __align__(16) bf16 g_hh[NTOT * EMBED];
__device__ __align__(16) bf16 g_hl[NTOT * EMBED];
__device__ __align__(16) bf16 g_WrT_h[3 * YW * CONV_IN];
__device__ __align__(16) bf16 g_WrT_l[3 * YW * CONV_IN];
__device__ __align__(16) bf16 g_WT0_h[EMBED * K0PAD];
__device__ __align__(16) bf16 g_WT0_l[EMBED * K0PAD];
__device__ __align__(16) bf16 g_WTl_h[2 * EMBED * KLPAD];
__device__ __align__(16) bf16 g_WTl_l[2 * EMBED * KLPAD];
__device__ __align__(16) bf16 g_rtT_h[3 * EMBED * CONV_IN];
__device__ __align__(16) bf16 g_rtT_l[3 * EMBED * CONV_IN];
__device__ __align__(16) bf16 g_fwT_h[EMBED * FINAL_IN];
__device__ __align__(16) bf16 g_fwT_l[EMBED * FINAL_IN];
__device__ float g_xin[NTOT * EMBED];
__device__ float g_msg[NTOT * EMBED];
__device__ float g_rootb[NTOT * EMBED];
__device__ float g_hf[NTOT * EMBED];
__device__ float g_Y[NTOT * YW];
__device__ float g_extra[NTOT * 40];
__device__ float g_sum[NTOT];
__device__ int   g_cnt[4096 * NCHUNK];
__device__ int   g_tot[4096];
__device__ int   g_off_s[4097];
__device__ int   g_eid_s[NEDGE];
__device__ int   g_off_t[4097];
__device__ int   g_eid_t[NEDGE];

// ---------------- helpers ----------------
__device__ __forceinline__ void bsplit(float v, bf16& h, bf16& l) {
    h = __float2bfloat16(v);
    l = __float2bfloat16(v - __bfloat162float(h));
}
__device__ __forceinline__ uint32_t smem_u32(const void* p) {
    uint32_t a;
    asm("{ .reg .u64 t; cvta.to.shared.u64 t, %1; cvt.u32.u64 %0, t; }" : "=r"(a) : "l"(p));
    return a;
}
__device__ __forceinline__ void cp16(uint32_t s, const void* g) {
    asm volatile("cp.async.cg.shared.global [%0], [%1], 16;" :: "r"(s), "l"(g));
}
__device__ __forceinline__ void ldsm4(uint32_t* r, uint32_t a) {
    asm volatile("ldmatrix.sync.aligned.m8n8.x4.shared.b16 {%0,%1,%2,%3}, [%4];"
                 : "=r"(r[0]), "=r"(r[1]), "=r"(r[2]), "=r"(r[3]) : "r"(a));
}
__device__ __forceinline__ void ldsm2(uint32_t* r, uint32_t a) {
    asm volatile("ldmatrix.sync.aligned.m8n8.x2.shared.b16 {%0,%1}, [%2];"
                 : "=r"(r[0]), "=r"(r[1]) : "r"(a));
}
__device__ __forceinline__ void mma16816(float* d, const uint32_t* a, const uint32_t* b) {
    asm volatile("mma.sync.aligned.m16n8k16.row.col.f32.bf16.bf16.f32 "
                 "{%0,%1,%2,%3}, {%4,%5,%6,%7}, {%8,%9}, {%0,%1,%2,%3};"
                 : "+f"(d[0]), "+f"(d[1]), "+f"(d[2]), "+f"(d[3])
                 : "r"(a[0]), "r"(a[1]), "r"(a[2]), "r"(a[3]), "r"(b[0]), "r"(b[1]));
}

// ======================================================================
// bf16 3-term GEMM: C = Ah*Bh + Ah*Bl + Al*Bh (+bias), fp32 accum.
// A: [m][k] rows, B: [n][k] rows. CTA tile (32*MT) x 128. K mult of 32.
// MT=4: 128x128 (warp 64x32, Al pass reloads Bh). MT=2: 64x128 (warp 32x32,
// Ah+Al both resident, B loaded once).
// ======================================================================
template <int MT>
__global__ void __launch_bounds__(256, 2) bgemm(
    const bf16* __restrict__ Ah, const bf16* __restrict__ Al, int lda, long long sA,
    const bf16* __restrict__ Bh, const bf16* __restrict__ Bl, int ldb, long long sB,
    float* __restrict__ C, int ldc, long long sC,
    const float* __restrict__ bias, int K)
{
    constexpr int ROWSA = 32 * MT;
    constexpr int SEGSA = ROWSA * 4;            // 16B segs per A matrix per chunk
    constexpr int SEGS  = 2 * SEGSA + 1024;     // + Bh,Bl (128 rows x 4 segs x 2)
    constexpr int PER   = SEGS / 256;
    constexpr int STAGE = 2 * ROWSA * 80 + 20480;

    extern __shared__ char smem[];
    const uint32_t sb = smem_u32(smem);
    const int tid = threadIdx.x, wid = tid >> 5, lane = tid & 31;
    const int wm = wid & 1, wn = wid >> 1;
    Ah += (long long)blockIdx.z * sA;  Al += (long long)blockIdx.z * sA;
    Bh += (long long)blockIdx.z * sB;  Bl += (long long)blockIdx.z * sB;
    C  += (long long)blockIdx.z * sC;
    const int m0 = blockIdx.y * ROWSA, n0 = blockIdx.x * 128;

    const int nch = K >> 5;
    float acc[MT][4][4];
#pragma unroll
    for (int i = 0; i < MT; i++)
#pragma unroll
        for (int j = 0; j < 4; j++)
#pragma unroll
            for (int q = 0; q < 4; q++) acc[i][j][q] = 0.f;

    auto issue = [&](int c, int buf) {
        const int k0 = c << 5;
#pragma unroll
        for (int i = 0; i < PER; i++) {
            int idx = tid + i * 256;
            uint32_t dst; const bf16* src;
            if (idx < SEGSA) {
                int r = idx >> 2, seg = idx & 3;
                dst = sb + buf * STAGE + r * 80 + seg * 16;
                src = Ah + (long long)(m0 + r) * lda + k0 + seg * 8;
            } else if (idx < 2 * SEGSA) {
                int j = idx - SEGSA; int r = j >> 2, seg = j & 3;
                dst = sb + buf * STAGE + ROWSA * 80 + r * 80 + seg * 16;
                src = Al + (long long)(m0 + r) * lda + k0 + seg * 8;
            } else {
                int j = idx - 2 * SEGSA;
                int mat = j >> 9, r = (j >> 2) & 127, seg = j & 3;
                dst = sb + buf * STAGE + 2 * ROWSA * 80 + mat * 10240 + r * 80 + seg * 16;
                src = (mat ? Bl : Bh) + (long long)(n0 + r) * ldb + k0 + seg * 8;
            }
            cp16(dst, src);
        }
        asm volatile("cp.async.commit_group;");
    };

    issue(0, 0);
    int cur = 0;
    for (int c = 0; c < nch; c++) {
        if (c + 1 < nch) { issue(c + 1, cur ^ 1); asm volatile("cp.async.wait_group 1;"); }
        else             { asm volatile("cp.async.wait_group 0;"); }
        __syncthreads();

        const uint32_t base   = sb + cur * STAGE;
        const uint32_t alBase = base + ROWSA * 80;
        const uint32_t bhBase = base + 2 * ROWSA * 80;
        const uint32_t blBase = bhBase + 10240;
        const uint32_t aRow = (uint32_t)(wm * 16 * MT) + (lane & 15);
        const uint32_t aK   = (lane >> 4) * 16;
        const uint32_t bRow = (uint32_t)(wn * 32) + (lane & 7);
        const uint32_t bK   = ((lane >> 3) & 1) * 16;
#pragma unroll
        for (int s = 0; s < 2; s++) {
            uint32_t a[MT][4], b[4][2];
            if (MT <= 2) {
                uint32_t al[MT][4];
#pragma unroll
                for (int mt = 0; mt < MT; mt++)
                    ldsm4(a[mt], base + (aRow + mt * 16) * 80 + s * 32 + aK);
#pragma unroll
                for (int mt = 0; mt < MT; mt++)
                    ldsm4(al[mt], alBase + (aRow + mt * 16) * 80 + s * 32 + aK);
#pragma unroll
                for (int nt = 0; nt < 4; nt++)
                    ldsm2(b[nt], bhBase + (bRow + nt * 8) * 80 + s * 32 + bK);
#pragma unroll
                for (int mt = 0; mt < MT; mt++)
#pragma unroll
                    for (int nt = 0; nt < 4; nt++) {
                        mma16816(acc[mt][nt], a[mt], b[nt]);
                        mma16816(acc[mt][nt], al[mt], b[nt]);
                    }
#pragma unroll
                for (int nt = 0; nt < 4; nt++)
                    ldsm2(b[nt], blBase + (bRow + nt * 8) * 80 + s * 32 + bK);
#pragma unroll
                for (int mt = 0; mt < MT; mt++)
#pragma unroll
                    for (int nt = 0; nt < 4; nt++) mma16816(acc[mt][nt], a[mt], b[nt]);
            } else {
#pragma unroll
                for (int mt = 0; mt < MT; mt++)
                    ldsm4(a[mt], base + (aRow + mt * 16) * 80 + s * 32 + aK);
#pragma unroll
                for (int nt = 0; nt < 4; nt++)
                    ldsm2(b[nt], bhBase + (bRow + nt * 8) * 80 + s * 32 + bK);
#pragma unroll
                for (int mt = 0; mt < MT; mt++)
#pragma unroll
                    for (int nt = 0; nt < 4; nt++) mma16816(acc[mt][nt], a[mt], b[nt]);
#pragma unroll
                for (int nt = 0; nt < 4; nt++)
                    ldsm2(b[nt], blBase + (bRow + nt * 8) * 80 + s * 32 + bK);
#pragma unroll
                for (int mt = 0; mt < MT; mt++)
#pragma unroll
                    for (int nt = 0; nt < 4; nt++) mma16816(acc[mt][nt], a[mt], b[nt]);
#pragma unroll
                for (int nt = 0; nt < 4; nt++)
                    ldsm2(b[nt], bhBase + (bRow + nt * 8) * 80 + s * 32 + bK);
#pragma unroll
                for (int mt = 0; mt < MT; mt++)
                    ldsm4(a[mt], alBase + (aRow + mt * 16) * 80 + s * 32 + aK);
#pragma unroll
                for (int mt = 0; mt < MT; mt++)
#pragma unroll
                    for (int nt = 0; nt < 4; nt++) mma16816(acc[mt][nt], a[mt], b[nt]);
            }
        }
        __syncthreads();
        cur ^= 1;
    }

    const int rbase = m0 + wm * 16 * MT + (lane >> 2);
    const int cbase = n0 + wn * 32 + 2 * (lane & 3);
#pragma unroll
    for (int mt = 0; mt < MT; mt++) {
#pragma unroll
        for (int nt = 0; nt < 4; nt++) {
            int r = rbase + mt * 16, cc = cbase + nt * 8;
            float b0 = 0.f, b1 = 0.f;
            if (bias) { b0 = bias[cc]; b1 = bias[cc + 1]; }
            float2 v0 = make_float2(acc[mt][nt][0] + b0, acc[mt][nt][1] + b1);
            float2 v1 = make_float2(acc[mt][nt][2] + b0, acc[mt][nt][3] + b1);
            *(float2*)(C + (long long)r * ldc + cc) = v0;
            *(float2*)(C + (long long)(r + 8) * ldc + cc) = v1;
        }
    }
}

// ---------------- transpose + split: fp32 [R][C] -> bf16 [C][Rpad] ----------------
__global__ void k_convT(const float* __restrict__ in, int R, int C, int ldin, long long sIn,
                        bf16* __restrict__ oh, bf16* __restrict__ ol, int Rpad, long long sOut) {
    __shared__ float t[32][33];
    in += (long long)blockIdx.z * sIn;
    oh += (long long)blockIdx.z * sOut;
    ol += (long long)blockIdx.z * sOut;
    int r0 = blockIdx.y * 32, c0 = blockIdx.x * 32;
    for (int i = threadIdx.y; i < 32; i += 8) {
        int r = r0 + i, c = c0 + threadIdx.x;
        t[i][threadIdx.x] = (r < R && c < C) ? in[(long long)r * ldin + c] : 0.f;
    }
    __syncthreads();
    for (int i = threadIdx.y; i < 32; i += 8) {
        int c = c0 + i, r = r0 + threadIdx.x;
        if (c < C && r < Rpad) {
            bf16 h, l; bsplit(t[threadIdx.x][i], h, l);
            oh[(long long)c * Rpad + r] = h;
            ol[(long long)c * Rpad + r] = l;
        }
    }
}
__global__ void k_convS(const float* __restrict__ in, bf16* __restrict__ oh,
                        bf16* __restrict__ ol, int n) {
    int i = blockIdx.x * 256 + threadIdx.x;
    if (i >= n) return;
    bf16 h, l; bsplit(in[i], h, l);
    oh[i] = h; ol[i] = l;
}

// ---------------- misc kernels ----------------
__global__ void k_rowsum(const float* __restrict__ Xt, float* __restrict__ rs) {
    int n = blockIdx.x;
    const float* row = Xt + (long long)n * NT;
    __shared__ float sm[256];
    float s = row[threadIdx.x] + row[threadIdx.x + 256];
    sm[threadIdx.x] = s; __syncthreads();
    for (int st = 128; st > 0; st >>= 1) {
        if (threadIdx.x < st) sm[threadIdx.x] += sm[threadIdx.x + st];
        __syncthreads();
    }
    if (threadIdx.x == 0) rs[n] = sm[0];
}
__global__ void k_colsum(const float* __restrict__ Xt, float* __restrict__ cs) {
    int b = blockIdx.x, t = threadIdx.x;
    float s = 0.f;
    const float* base = Xt + (long long)b * NS * NT + t;
    for (int srow = 0; srow < NS; srow++) s += base[srow * NT];
    cs[b * NT + t] = s;
}
__global__ void k_extra(const float* __restrict__ sums, const float* __restrict__ tvec,
                        float* __restrict__ extra) {
    int n = blockIdx.x * blockDim.x + threadIdx.x;
    if (n >= NTOT) return;
    float x = sums[n] * 0.1f;
    float tb = tvec[(n >> 9) & 7];
    const float c = -1.0233711524418064f;
#pragma unroll
    for (int i = 0; i < 10; i++) {
        float f = expf(c * (float)i);
        float ax = x * f, at = tb * f;
        extra[n * 40 + i]      = sinf(ax);
        extra[n * 40 + 10 + i] = cosf(ax);
        extra[n * 40 + 20 + i] = sinf(at);
        extra[n * 40 + 30 + i] = cosf(at);
    }
}
__global__ void k_copyx(const float* __restrict__ xs, const float* __restrict__ xt,
                        bf16* __restrict__ fh, bf16* __restrict__ fl) {
    int n = blockIdx.x;
    const float* x = (n < NSRC) ? xs + (long long)n * ORI : xt + (long long)(n - NSRC) * ORI;
    for (int c = threadIdx.x; c < ORI; c += 256) {
        bf16 h, l; bsplit(x[c], h, l);
        fh[(long long)n * FINAL_IN + c] = h;
        fl[(long long)n * FINAL_IN + c] = l;
    }
}
__global__ void k_xcat0(const float* __restrict__ xs, const float* __restrict__ xt,
                        const float* __restrict__ extra,
                        bf16* __restrict__ oh, bf16* __restrict__ ol) {
    int n = blockIdx.x;
    const float* x = (n < NSRC) ? xs + (long long)n * ORI : xt + (long long)(n - NSRC) * ORI;
    for (int c = threadIdx.x; c < K0PAD; c += 256) {
        float v = (c < 1024) ? x[c] : ((c < 1064) ? extra[n * 40 + c - 1024] : 0.f);
        bf16 h, l; bsplit(v, h, l);
        oh[(long long)n * K0PAD + c] = h;
        ol[(long long)n * K0PAD + c] = l;
    }
}
__global__ void k_xcatL(const bf16* __restrict__ fh, const bf16* __restrict__ fl,
                        const float* __restrict__ extra,
                        bf16* __restrict__ oh, bf16* __restrict__ ol, int l) {
    int n = blockIdx.x, c = threadIdx.x;   // 192 threads
    bf16 h = __float2bfloat16(0.f), lo = h;
    if (c < 128) {
        long long o = (long long)n * FINAL_IN + ORI + (l - 1) * EMBED + c;
        h = fh[o]; lo = fl[o];
    } else if (c < 168) {
        bsplit(extra[n * 40 + (c - 128)], h, lo);
    }
    oh[(long long)n * KLPAD + c] = h;
    ol[(long long)n * KLPAD + c] = lo;
}
__global__ void k_cat(const float* __restrict__ xin, const float* __restrict__ msg,
                      bf16* __restrict__ oh, bf16* __restrict__ ol) {
    int n = blockIdx.x, d = threadIdx.x;
    float v;
    if (d < EMBED) v = xin[n * EMBED + d];
    else           v = xin[n * EMBED + d - EMBED] - msg[n * EMBED + d - EMBED];
    bf16 h, l; bsplit(v, h, l);
    oh[(long long)n * CONV_IN + d] = h;
    ol[(long long)n * CONV_IN + d] = l;
}

// ----- stable CSR build -----
__global__ void k_count(const int* __restrict__ ei, int* __restrict__ cnt) {
    int e = blockIdx.x * 256 + threadIdx.x;
    int d = ei[NEDGE + e];
    atomicAdd(&cnt[d * NCHUNK + (e >> 5)], 1);
}
__global__ void k_colscan(int* __restrict__ cnt, int* __restrict__ tot) {
    int d = blockIdx.x * 256 + threadIdx.x;
    if (d >= 4096) return;
    int run = 0;
    int* row = cnt + d * NCHUNK;
    for (int c = 0; c < NCHUNK; c++) { int v = row[c]; row[c] = run; run += v; }
    tot[d] = run;
}
__global__ void k_scan(const int* __restrict__ tot, int* __restrict__ off) {
    __shared__ int s[1024];
    int tid = threadIdx.x;
    int v[4]; int sum = 0;
#pragma unroll
    for (int i = 0; i < 4; i++) { v[i] = tot[tid * 4 + i]; sum += v[i]; }
    s[tid] = sum; __syncthreads();
    for (int d = 1; d < 1024; d <<= 1) {
        int x = (tid >= d) ? s[tid - d] : 0;
        __syncthreads();
        s[tid] += x;
        __syncthreads();
    }
    int run = (tid == 0) ? 0 : s[tid - 1];
#pragma unroll
    for (int i = 0; i < 4; i++) { off[tid * 4 + i] = run; run += v[i]; }
    if (tid == 1023) off[4096] = run;
}
__global__ void k_place(const int* __restrict__ ei, const int* __restrict__ off,
                        int* __restrict__ cnt, int* __restrict__ eid) {
    int c = blockIdx.x * 256 + threadIdx.x;
    if (c >= NCHUNK) return;
    for (int j = 0; j < CHUNK; j++) {
        int e = c * CHUNK + j;
        int d = ei[NEDGE + e];
        int r = cnt[d * NCHUNK + c];
        cnt[d * NCHUNK + c] = r + 1;
        eid[off[d] + r] = e;
    }
}

// ----- spline gather + mean + root + tanh -> feat hi/lo -----
__global__ void k_spline_agg(const float* __restrict__ Y, const float* __restrict__ rootb,
                             const int* __restrict__ off, const int* __restrict__ eid,
                             const int* __restrict__ ei, const float* __restrict__ ea,
                             bf16* __restrict__ oh, bf16* __restrict__ ol) {
    int n = blockIdx.x, d = threadIdx.x;       // 128
    int beg = off[n], end = off[n + 1];

    auto contrib = [&](int e) -> float {
        int src = ei[e];
        float v0 = ea[e * 2] * 4.f, v1 = ea[e * 2 + 1] * 4.f;
        float l0 = floorf(v0), l1 = floorf(v1);
        float f0 = v0 - l0, f1 = v1 - l1;
        int i0 = (int)l0, i1 = (int)l1;
        const float* Ys = Y + (long long)src * YW;
        float r = 0.f;
#pragma unroll
        for (int s1 = 0; s1 < 2; s1++)
#pragma unroll
            for (int s0 = 0; s0 < 2; s0++) {
                int a0 = min(max(i0 + s0, 0), 4);
                int a1 = min(max(i1 + s1, 0), 4);
                float w = (s0 ? f0 : 1.f - f0) * (s1 ? f1 : 1.f - f1);
                r += w * Ys[(a0 + 5 * a1) * EMBED + d];
            }
        return r;
    };

    float acc0 = 0.f, acc1 = 0.f;
    int j = beg;
    for (; j + 2 <= end; j += 2) {
        acc0 += contrib(eid[j]);
        acc1 += contrib(eid[j + 1]);
    }
    if (j < end) acc0 += contrib(eid[j]);
    float acc = acc0 + acc1;

    float deg = (float)(end - beg);
    acc = acc / fmaxf(deg, 1.f);
    float v = tanhf(acc + rootb[n * EMBED + d]);
    bf16 h, l; bsplit(v, h, l);
    oh[(long long)n * FINAL_IN + d] = h;
    ol[(long long)n * FINAL_IN + d] = l;
}

__global__ void k_softmax(float* __restrict__ out) {
    int r = blockIdx.x;
    float* row = out + (long long)r * NT;
    __shared__ float sm[256];
    int tid = threadIdx.x;
    float a = row[tid], b = row[tid + 256];
    sm[tid] = fmaxf(a, b); __syncthreads();
    for (int s = 128; s > 0; s >>= 1) {
        if (tid < s) sm[tid] = fmaxf(sm[tid], sm[tid + s]);
        __syncthreads();
    }
    float mx = sm[0]; __syncthreads();
    float ea = expf(a - mx), eb = expf(b - mx);
    sm[tid] = ea + eb; __syncthreads();
    for (int s = 128; s > 0; s >>= 1) {
        if (tid < s) sm[tid] += sm[tid + s];
        __syncthreads();
    }
    float inv = 1.f / sm[0];
    row[tid] = ea * inv;
    row[tid + 256] = eb * inv;
}

// ---------------- host ----------------
#define GSMEM4 (2 * (2 * 128 * 80 + 20480))   // 81920
#define GSMEM2 (2 * (2 * 64 * 80 + 20480))    // 61440

static void build_csr(const int* ei, int* off, int* eid, int* cnt, int* tot) {
    cudaMemsetAsync(cnt, 0, 4096 * NCHUNK * sizeof(int));
    k_count<<<NEDGE / 256, 256>>>(ei, cnt);
    k_colscan<<<16, 256>>>(cnt, tot);
    k_scan<<<1, 1024>>>(tot, off);
    k_place<<<4, 256>>>(ei, off, cnt, eid);
}

#define GETSYM(v, s) cudaGetSymbolAddress((void**)&v, s)

extern "C" void kernel_launch(void* const* d_in, const int* in_sizes, int n_in,
                              void* d_out, int out_size) {
    const float* t_in      = (const float*)d_in[0];
    const float* Xt        = (const float*)d_in[1];
    const float* x_s       = (const float*)d_in[2];
    const float* x_t       = (const float*)d_in[3];
    const float* ea_s      = (const float*)d_in[4];
    const float* ea_t      = (const float*)d_in[5];
    const float* lin0_w    = (const float*)d_in[6];
    const float* lin0_b    = (const float*)d_in[7];
    const float* lin_w     = (const float*)d_in[8];
    const float* lin_b     = (const float*)d_in[9];
    const float* conv_w    = (const float*)d_in[10];
    const float* conv_root = (const float*)d_in[11];
    const float* conv_bias = (const float*)d_in[12];
    const float* final_w   = (const float*)d_in[13];
    const float* final_b   = (const float*)d_in[14];
    const int*   ei_s      = (const int*)d_in[15];
    const int*   ei_t      = (const int*)d_in[16];
    float* out = (float*)d_out;

    cudaFuncSetAttribute(bgemm<4>, cudaFuncAttributeMaxDynamicSharedMemorySize, GSMEM4);
    cudaFuncSetAttribute(bgemm<2>, cudaFuncAttributeMaxDynamicSharedMemorySize, GSMEM2);

    bf16 *xcat_h, *xcat_l, *Xh, *Xl, *XTh, *XTl, *xinT_h, *xinT_l, *cat_h, *cat_l;
    bf16 *feat_h, *feat_l, *hh, *hl, *WrT_h, *WrT_l, *WT0_h, *WT0_l, *WTl_h, *WTl_l;
    bf16 *rtT_h, *rtT_l, *fwT_h, *fwT_l;
    float *xin, *msg, *rootb, *hf, *Y, *extra, *sums;
    int *cnt, *tot, *off_s, *eid_s, *off_t, *eid_t;
    GETSYM(xcat_h, g_xcat_h); GETSYM(xcat_l, g_xcat_l);
    GETSYM(Xh, g_Xh); GETSYM(Xl, g_Xl); GETSYM(XTh, g_XTh); GETSYM(XTl, g_XTl);
    GETSYM(xinT_h, g_xinT_h); GETSYM(xinT_l, g_xinT_l);
    GETSYM(cat_h, g_cat_h); GETSYM(cat_l, g_cat_l);
    GETSYM(feat_h, g_feat_h); GETSYM(feat_l, g_feat_l);
    GETSYM(hh, g_hh); GETSYM(hl, g_hl);
    GETSYM(WrT_h, g_WrT_h); GETSYM(WrT_l, g_WrT_l);
    GETSYM(WT0_h, g_WT0_h); GETSYM(WT0_l, g_WT0_l);
    GETSYM(WTl_h, g_WTl_h); GETSYM(WTl_l, g_WTl_l);
    GETSYM(rtT_h, g_rtT_h); GETSYM(rtT_l, g_rtT_l);
    GETSYM(fwT_h, g_fwT_h); GETSYM(fwT_l, g_fwT_l);
    GETSYM(xin, g_xin); GETSYM(msg, g_msg); GETSYM(rootb, g_rootb);
    GETSYM(hf, g_hf); GETSYM(Y, g_Y); GETSYM(extra, g_extra); GETSYM(sums, g_sum);
    GETSYM(cnt, g_cnt); GETSYM(tot, g_tot);
    GETSYM(off_s, g_off_s); GETSYM(eid_s, g_eid_s);
    GETSYM(off_t, g_off_t); GETSYM(eid_t, g_eid_t);

    dim3 tb(32, 8);

    // ---- phase A: minimal chain so launch #5 (ncu -s 5 -c 1) is a bgemm ----
    k_rowsum<<<NSRC, 256>>>(Xt, sums);                                        // 0
    k_colsum<<<BATCH, 512>>>(Xt, sums + NSRC);                                // 1
    k_extra<<<32, 256>>>(sums, t_in, extra);                                  // 2
    k_xcat0<<<NTOT, 256>>>(x_s, x_t, extra, xcat_h, xcat_l);                  // 3
    k_convT<<<dim3(4, K0PAD / 32, 1), tb>>>(lin0_w, 1064, EMBED, EMBED, 0,
                                            WT0_h, WT0_l, K0PAD, 0);          // 4
    bgemm<2><<<dim3(1, NTOT / 64, 1), 256, GSMEM2>>>(                         // 5 (profiled)
        xcat_h, xcat_l, K0PAD, 0, WT0_h, WT0_l, K0PAD, 0,
        xin, EMBED, 0, lin0_b, K0PAD);

    // ---- phase B: rest of prep ----
    k_convS<<<(BATCH * NS * NT + 255) / 256, 256>>>(Xt, Xh, Xl, BATCH * NS * NT);
    k_convT<<<dim3(16, 16, BATCH), tb>>>(Xt, NS, NT, NT, (long long)NS * NT,
                                         XTh, XTl, NS, (long long)NS * NT);
    k_convT<<<dim3(4, KLPAD / 32, 2), tb>>>(lin_w, 168, EMBED, EMBED, 168 * EMBED,
                                            WTl_h, WTl_l, KLPAD, (long long)EMBED * KLPAD);
    k_convT<<<dim3(4, 8, 75), tb>>>(conv_w, CONV_IN, EMBED, EMBED, (long long)CONV_IN * EMBED,
                                    WrT_h, WrT_l, CONV_IN, (long long)EMBED * CONV_IN);
    k_convT<<<dim3(4, 8, 3), tb>>>(conv_root, CONV_IN, EMBED, EMBED, (long long)CONV_IN * EMBED,
                                   rtT_h, rtT_l, CONV_IN, (long long)EMBED * CONV_IN);
    k_convT<<<dim3(4, FINAL_IN / 32, 1), tb>>>(final_w, FINAL_IN, EMBED, EMBED, 0,
                                               fwT_h, fwT_l, FINAL_IN, 0);
    k_copyx<<<NTOT, 256>>>(x_s, x_t, feat_h, feat_l);
    build_csr(ei_s, off_s, eid_s, cnt, tot);
    build_csr(ei_t, off_t, eid_t, cnt, tot);

    for (int l = 0; l < 3; l++) {
        if (l > 0) {
            k_xcatL<<<NTOT, 192>>>(feat_h, feat_l, extra, xcat_h, xcat_l, l);
            const bf16* wh = WTl_h + (long long)(l - 1) * EMBED * KLPAD;
            const bf16* wl = WTl_l + (long long)(l - 1) * EMBED * KLPAD;
            bgemm<2><<<dim3(1, NTOT / 64, 1), 256, GSMEM2>>>(
                xcat_h, xcat_l, KLPAD, 0, wh, wl, KLPAD, 0,
                xin, EMBED, 0, lin_b + (l - 1) * EMBED, KLPAD);
        }
        // xinT (fp32 -> transposed split)
        k_convT<<<dim3(4, 256, 1), tb>>>(xin, NTOT, EMBED, EMBED, 0,
                                         xinT_h, xinT_l, NTOT, 0);
        // tgt_msg: A = Xt[b], B = xinT target cols
        bgemm<2><<<dim3(1, NS / 64, 8), 256, GSMEM2>>>(
            Xh, Xl, NT, (long long)NS * NT,
            xinT_h + NSRC, xinT_l + NSRC, NTOT, NS,
            msg, EMBED, (long long)NS * EMBED, nullptr, NT);
        // src_msg: A = Xt[b]^T, B = xinT source cols
        bgemm<2><<<dim3(1, NT / 64, 8), 256, GSMEM2>>>(
            XTh, XTl, NS, (long long)NS * NT,
            xinT_h, xinT_l, NTOT, NS,
            msg + (long long)NSRC * EMBED, EMBED, (long long)NT * EMBED, nullptr, NS);

        k_cat<<<NTOT, 256>>>(xin, msg, cat_h, cat_l);

        // Y = cat @ Wr[l]
        bgemm<4><<<dim3(YW / 128, NTOT / 128, 1), 256, GSMEM4>>>(
            cat_h, cat_l, CONV_IN, 0,
            WrT_h + (long long)l * YW * CONV_IN, WrT_l + (long long)l * YW * CONV_IN, CONV_IN, 0,
            Y, YW, 0, nullptr, CONV_IN);
        // rootb = cat @ root + bias
        bgemm<2><<<dim3(1, NTOT / 64, 1), 256, GSMEM2>>>(
            cat_h, cat_l, CONV_IN, 0,
            rtT_h + (long long)l * EMBED * CONV_IN, rtT_l + (long long)l * EMBED * CONV_IN, CONV_IN, 0,
            rootb, EMBED, 0, conv_bias + l * EMBED, CONV_IN);

        k_spline_agg<<<NSRC, 128>>>(Y, rootb, off_s, eid_s, ei_s, ea_s,
                                    feat_h + ORI + l * EMBED, feat_l + ORI + l * EMBED);
        k_spline_agg<<<NSRC, 128>>>(Y + (long long)NSRC * YW, rootb + (long long)NSRC * EMBED,
                                    off_t, eid_t, ei_t, ea_t,
                                    feat_h + (long long)NSRC * FINAL_IN + ORI + l * EMBED,
                                    feat_l + (long long)NSRC * FINAL_IN + ORI + l * EMBED);
    }

    // h = feat @ final_w + final_b
    bgemm<2><<<dim3(1, NTOT / 64, 1), 256, GSMEM2>>>(
        feat_h, feat_l, FINAL_IN, 0, fwT_h, fwT_l, FINAL_IN, 0,
        hf, EMBED, 0, final_b, FINAL_IN);
    k_convS<<<(NTOT * EMBED + 255) / 256, 256>>>(hf, hh, hl, NTOT * EMBED);

    // sim = h_s @ h_t^T per batch
    bgemm<4><<<dim3(4, 4, 8), 256, GSMEM4>>>(
        hh, hl, EMBED, (long long)NS * EMBED,
        hh + (long long)NSRC * EMBED, hl + (long long)NSRC * EMBED, EMBED, (long long)NT * EMBED,
        out, NT, (long long)NS * NT, nullptr, EMBED);

    k_softmax<<<NSRC, 256>>>(out);
}

// round 6
// speedup vs baseline: 2.9375x; 1.4733x over previous
#include <cuda_runtime.h>
#include <cuda_bf16.h>
#include <math.h>
#include <stdint.h>

// ---------------- problem constants ----------------
#define BATCH 8
#define NS 512
#define NT 512
#define NSRC 4096
#define NTOT 8192
#define NEDGE 32768
#define EMBED 128
#define ORI 1024
#define CONV_IN 256
#define FINAL_IN 1408
#define KK 25
#define YW 3200
#define CHUNK 32
#define NCHUNK 1024
#define K0PAD 1088
#define KLPAD 192

typedef __nv_bfloat16 bf16;

// ---------------- device scratch ----------------
__device__ __align__(16) bf16 g_xcat_h[NTOT * K0PAD];
__device__ __align__(16) bf16 g_xcat_l[NTOT * K0PAD];
__device__ __align__(16) bf16 g_Xh[BATCH * NS * NT];
__device__ __align__(16) bf16 g_Xl[BATCH * NS * NT];
__device__ __align__(16) bf16 g_XTh[BATCH * NS * NT];
__device__ __align__(16) bf16 g_XTl[BATCH * NS * NT];
__device__ __align__(16) bf16 g_xinT_h[EMBED * NTOT];
__device__ __align__(16) bf16 g_xinT_l[EMBED * NTOT];
__device__ __align__(16) bf16 g_cat_h[NTOT * CONV_IN];
__device__ __align__(16) bf16 g_cat_l[NTOT * CONV_IN];
__device__ __align__(16) bf16 g_feat_h[NTOT * FINAL_IN];
__device__ __align__(16) bf16 g_feat_l[NTOT * FINAL_IN];
__device__ __align__(16) bf16 g_hh[NTOT * EMBED];
__device__ __align__(16) bf16 g_hl[NTOT * EMBED];
__device__ __align__(16) bf16 g_WrT_h[3 * YW * CONV_IN];
__device__ __align__(16) bf16 g_WrT_l[3 * YW * CONV_IN];
__device__ __align__(16) bf16 g_WT0_h[EMBED * K0PAD];
__device__ __align__(16) bf16 g_WT0_l[EMBED * K0PAD];
__device__ __align__(16) bf16 g_WTl_h[2 * EMBED * KLPAD];
__device__ __align__(16) bf16 g_WTl_l[2 * EMBED * KLPAD];
__device__ __align__(16) bf16 g_rtT_h[3 * EMBED * CONV_IN];
__device__ __align__(16) bf16 g_rtT_l[3 * EMBED * CONV_IN];
__device__ __align__(16) bf16 g_fwT_h[EMBED * FINAL_IN];
__device__ __align__(16) bf16 g_fwT_l[EMBED * FINAL_IN];
__device__ float g_xin[NTOT * EMBED];
__device__ float g_msg[NTOT * EMBED];
__device__ float g_rootb[NTOT * EMBED];
__device__ float g_hf[NTOT * EMBED];
__device__ float g_Y[NTOT * YW];
__device__ float g_extra[NTOT * 40];
__device__ float g_sum[NTOT];
__device__ int   g_cnt[NCHUNK * 4096];           // [chunk][dst] (coalesced scans)
__device__ int   g_tot[4096];
__device__ int   g_off_s[4097];
__device__ int   g_eid_s[NEDGE];
__device__ int   g_off_t[4097];
__device__ int   g_eid_t[NEDGE];

// ---------------- helpers ----------------
__device__ __forceinline__ void bsplit(float v, bf16& h, bf16& l) {
    h = __float2bfloat16(v);
    l = __float2bfloat16(v - __bfloat162float(h));
}
__device__ __forceinline__ uint32_t smem_u32(const void* p) {
    uint32_t a;
    asm("{ .reg .u64 t; cvta.to.shared.u64 t, %1; cvt.u32.u64 %0, t; }" : "=r"(a) : "l"(p));
    return a;
}
__device__ __forceinline__ void cp16(uint32_t s, const void* g) {
    asm volatile("cp.async.cg.shared.global [%0], [%1], 16;" :: "r"(s), "l"(g));
}
__device__ __forceinline__ void ldsm4(uint32_t* r, uint32_t a) {
    asm volatile("ldmatrix.sync.aligned.m8n8.x4.shared.b16 {%0,%1,%2,%3}, [%4];"
                 : "=r"(r[0]), "=r"(r[1]), "=r"(r[2]), "=r"(r[3]) : "r"(a));
}
__device__ __forceinline__ void ldsm2(uint32_t* r, uint32_t a) {
    asm volatile("ldmatrix.sync.aligned.m8n8.x2.shared.b16 {%0,%1}, [%2];"
                 : "=r"(r[0]), "=r"(r[1]) : "r"(a));
}
__device__ __forceinline__ void mma16816(float* d, const uint32_t* a, const uint32_t* b) {
    asm volatile("mma.sync.aligned.m16n8k16.row.col.f32.bf16.bf16.f32 "
                 "{%0,%1,%2,%3}, {%4,%5,%6,%7}, {%8,%9}, {%0,%1,%2,%3};"
                 : "+f"(d[0]), "+f"(d[1]), "+f"(d[2]), "+f"(d[3])
                 : "r"(a[0]), "r"(a[1]), "r"(a[2]), "r"(a[3]), "r"(b[0]), "r"(b[1]));
}

// ======================================================================
// bf16 3-term GEMM: C = Ah*Bh + Ah*Bl + Al*Bh (+bias), fp32 accum.
// A: [m][k] rows, B: [n][k] rows. CTA tile (32*MT) x 128. K mult of 32.
// Per-thread staging pointers are computed ONCE; the chunk loop only does
// cp.async + pointer increments.
// ======================================================================
template <int MT>
__global__ void __launch_bounds__(256, 2) bgemm(
    const bf16* __restrict__ Ah, const bf16* __restrict__ Al, int lda, long long sA,
    const bf16* __restrict__ Bh, const bf16* __restrict__ Bl, int ldb, long long sB,
    float* __restrict__ C, int ldc, long long sC,
    const float* __restrict__ bias, int K)
{
    constexpr int ROWSA = 32 * MT;
    constexpr int SEGSA = ROWSA * 4;            // 16B segs per A matrix per chunk
    constexpr int SEGS  = 2 * SEGSA + 1024;     // + Bh,Bl (128 rows x 4 segs x 2)
    constexpr int PER   = SEGS / 256;
    constexpr int STAGE = 2 * ROWSA * 80 + 20480;

    extern __shared__ char smem[];
    const uint32_t sb = smem_u32(smem);
    const int tid = threadIdx.x, wid = tid >> 5, lane = tid & 31;
    const int wm = wid & 1, wn = wid >> 1;
    Ah += (long long)blockIdx.z * sA;  Al += (long long)blockIdx.z * sA;
    Bh += (long long)blockIdx.z * sB;  Bl += (long long)blockIdx.z * sB;
    C  += (long long)blockIdx.z * sC;
    const int m0 = blockIdx.y * ROWSA, n0 = blockIdx.x * 128;

    // ---- precompute per-thread staging roles (once) ----
    const bf16* gp[PER];
    uint32_t sd[PER];
#pragma unroll
    for (int i = 0; i < PER; i++) {
        int idx = tid + i * 256;
        if (idx < SEGSA) {
            int r = idx >> 2, sg = idx & 3;
            gp[i] = Ah + (long long)(m0 + r) * lda + sg * 8;
            sd[i] = sb + r * 80 + sg * 16;
        } else if (idx < 2 * SEGSA) {
            int j = idx - SEGSA; int r = j >> 2, sg = j & 3;
            gp[i] = Al + (long long)(m0 + r) * lda + sg * 8;
            sd[i] = sb + ROWSA * 80 + r * 80 + sg * 16;
        } else {
            int j = idx - 2 * SEGSA;
            int mat = j >> 9, r = (j >> 2) & 127, sg = j & 3;
            gp[i] = (mat ? Bl : Bh) + (long long)(n0 + r) * ldb + sg * 8;
            sd[i] = sb + 2 * ROWSA * 80 + mat * 10240 + r * 80 + sg * 16;
        }
    }

    const int nch = K >> 5;
    float acc[MT][4][4];
#pragma unroll
    for (int i = 0; i < MT; i++)
#pragma unroll
        for (int j = 0; j < 4; j++)
#pragma unroll
            for (int q = 0; q < 4; q++) acc[i][j][q] = 0.f;

    auto issue = [&](uint32_t bufoff) {
#pragma unroll
        for (int i = 0; i < PER; i++) { cp16(sd[i] + bufoff, gp[i]); gp[i] += 32; }
        asm volatile("cp.async.commit_group;");
    };

    issue(0);
    int cur = 0;
    for (int c = 0; c < nch; c++) {
        if (c + 1 < nch) { issue((cur ^ 1) * STAGE); asm volatile("cp.async.wait_group 1;"); }
        else             { asm volatile("cp.async.wait_group 0;"); }
        __syncthreads();

        const uint32_t base   = sb + cur * STAGE;
        const uint32_t alBase = base + ROWSA * 80;
        const uint32_t bhBase = base + 2 * ROWSA * 80;
        const uint32_t blBase = bhBase + 10240;
        const uint32_t aRow = (uint32_t)(wm * 16 * MT) + (lane & 15);
        const uint32_t aK   = (lane >> 4) * 16;
        const uint32_t bRow = (uint32_t)(wn * 32) + (lane & 7);
        const uint32_t bK   = ((lane >> 3) & 1) * 16;
#pragma unroll
        for (int s = 0; s < 2; s++) {
            uint32_t a[MT][4], b[4][2];
            if (MT <= 2) {
                uint32_t al[MT][4];
#pragma unroll
                for (int mt = 0; mt < MT; mt++)
                    ldsm4(a[mt], base + (aRow + mt * 16) * 80 + s * 32 + aK);
#pragma unroll
                for (int mt = 0; mt < MT; mt++)
                    ldsm4(al[mt], alBase + (aRow + mt * 16) * 80 + s * 32 + aK);
#pragma unroll
                for (int nt = 0; nt < 4; nt++)
                    ldsm2(b[nt], bhBase + (bRow + nt * 8) * 80 + s * 32 + bK);
#pragma unroll
                for (int mt = 0; mt < MT; mt++)
#pragma unroll
                    for (int nt = 0; nt < 4; nt++) {
                        mma16816(acc[mt][nt], a[mt], b[nt]);
                        mma16816(acc[mt][nt], al[mt], b[nt]);
                    }
#pragma unroll
                for (int nt = 0; nt < 4; nt++)
                    ldsm2(b[nt], blBase + (bRow + nt * 8) * 80 + s * 32 + bK);
#pragma unroll
                for (int mt = 0; mt < MT; mt++)
#pragma unroll
                    for (int nt = 0; nt < 4; nt++) mma16816(acc[mt][nt], a[mt], b[nt]);
            } else {
#pragma unroll
                for (int mt = 0; mt < MT; mt++)
                    ldsm4(a[mt], base + (aRow + mt * 16) * 80 + s * 32 + aK);
#pragma unroll
                for (int nt = 0; nt < 4; nt++)
                    ldsm2(b[nt], bhBase + (bRow + nt * 8) * 80 + s * 32 + bK);
#pragma unroll
                for (int mt = 0; mt < MT; mt++)
#pragma unroll
                    for (int nt = 0; nt < 4; nt++) mma16816(acc[mt][nt], a[mt], b[nt]);
#pragma unroll
                for (int nt = 0; nt < 4; nt++)
                    ldsm2(b[nt], blBase + (bRow + nt * 8) * 80 + s * 32 + bK);
#pragma unroll
                for (int mt = 0; mt < MT; mt++)
#pragma unroll
                    for (int nt = 0; nt < 4; nt++) mma16816(acc[mt][nt], a[mt], b[nt]);
#pragma unroll
                for (int nt = 0; nt < 4; nt++)
                    ldsm2(b[nt], bhBase + (bRow + nt * 8) * 80 + s * 32 + bK);
#pragma unroll
                for (int mt = 0; mt < MT; mt++)
                    ldsm4(a[mt], alBase + (aRow + mt * 16) * 80 + s * 32 + aK);
#pragma unroll
                for (int mt = 0; mt < MT; mt++)
#pragma unroll
                    for (int nt = 0; nt < 4; nt++) mma16816(acc[mt][nt], a[mt], b[nt]);
            }
        }
        __syncthreads();
        cur ^= 1;
    }

    const int rbase = m0 + wm * 16 * MT + (lane >> 2);
    const int cbase = n0 + wn * 32 + 2 * (lane & 3);
#pragma unroll
    for (int mt = 0; mt < MT; mt++) {
#pragma unroll
        for (int nt = 0; nt < 4; nt++) {
            int r = rbase + mt * 16, cc = cbase + nt * 8;
            float b0 = 0.f, b1 = 0.f;
            if (bias) { b0 = bias[cc]; b1 = bias[cc + 1]; }
            float2 v0 = make_float2(acc[mt][nt][0] + b0, acc[mt][nt][1] + b1);
            float2 v1 = make_float2(acc[mt][nt][2] + b0, acc[mt][nt][3] + b1);
            *(float2*)(C + (long long)r * ldc + cc) = v0;
            *(float2*)(C + (long long)(r + 8) * ldc + cc) = v1;
        }
    }
}

// ---------------- transpose + split: fp32 [R][C] -> bf16 [C][Rpad] ----------------
__global__ void k_convT(const float* __restrict__ in, int R, int C, int ldin, long long sIn,
                        bf16* __restrict__ oh, bf16* __restrict__ ol, int Rpad, long long sOut) {
    __shared__ float t[32][33];
    in += (long long)blockIdx.z * sIn;
    oh += (long long)blockIdx.z * sOut;
    ol += (long long)blockIdx.z * sOut;
    int r0 = blockIdx.y * 32, c0 = blockIdx.x * 32;
    for (int i = threadIdx.y; i < 32; i += 8) {
        int r = r0 + i, c = c0 + threadIdx.x;
        t[i][threadIdx.x] = (r < R && c < C) ? in[(long long)r * ldin + c] : 0.f;
    }
    __syncthreads();
    for (int i = threadIdx.y; i < 32; i += 8) {
        int c = c0 + i, r = r0 + threadIdx.x;
        if (c < C && r < Rpad) {
            bf16 h, l; bsplit(t[threadIdx.x][i], h, l);
            oh[(long long)c * Rpad + r] = h;
            ol[(long long)c * Rpad + r] = l;
        }
    }
}
__global__ void k_convS(const float* __restrict__ in, bf16* __restrict__ oh,
                        bf16* __restrict__ ol, int n) {
    int i = blockIdx.x * 256 + threadIdx.x;
    if (i >= n) return;
    bf16 h, l; bsplit(in[i], h, l);
    oh[i] = h; ol[i] = l;
}

// ---------------- misc kernels ----------------
__global__ void k_rowsum(const float* __restrict__ Xt, float* __restrict__ rs) {
    int n = blockIdx.x;
    const float* row = Xt + (long long)n * NT;
    __shared__ float sm[256];
    float s = row[threadIdx.x] + row[threadIdx.x + 256];
    sm[threadIdx.x] = s; __syncthreads();
    for (int st = 128; st > 0; st >>= 1) {
        if (threadIdx.x < st) sm[threadIdx.x] += sm[threadIdx.x + st];
        __syncthreads();
    }
    if (threadIdx.x == 0) rs[n] = sm[0];
}
__global__ void k_colsum(const float* __restrict__ Xt, float* __restrict__ cs) {
    int b = blockIdx.x, t = threadIdx.x;
    float s = 0.f;
    const float* base = Xt + (long long)b * NS * NT + t;
    for (int srow = 0; srow < NS; srow++) s += base[srow * NT];
    cs[b * NT + t] = s;
}
__global__ void k_extra(const float* __restrict__ sums, const float* __restrict__ tvec,
                        float* __restrict__ extra) {
    int n = blockIdx.x * blockDim.x + threadIdx.x;
    if (n >= NTOT) return;
    float x = sums[n] * 0.1f;
    float tb = tvec[(n >> 9) & 7];
    const float c = -1.0233711524418064f;
#pragma unroll
    for (int i = 0; i < 10; i++) {
        float f = expf(c * (float)i);
        float ax = x * f, at = tb * f;
        extra[n * 40 + i]      = sinf(ax);
        extra[n * 40 + 10 + i] = cosf(ax);
        extra[n * 40 + 20 + i] = sinf(at);
        extra[n * 40 + 30 + i] = cosf(at);
    }
}
__global__ void k_copyx(const float* __restrict__ xs, const float* __restrict__ xt,
                        bf16* __restrict__ fh, bf16* __restrict__ fl) {
    int n = blockIdx.x;
    const float* x = (n < NSRC) ? xs + (long long)n * ORI : xt + (long long)(n - NSRC) * ORI;
    for (int c = threadIdx.x; c < ORI; c += 256) {
        bf16 h, l; bsplit(x[c], h, l);
        fh[(long long)n * FINAL_IN + c] = h;
        fl[(long long)n * FINAL_IN + c] = l;
    }
}
__global__ void k_xcat0(const float* __restrict__ xs, const float* __restrict__ xt,
                        const float* __restrict__ extra,
                        bf16* __restrict__ oh, bf16* __restrict__ ol) {
    int n = blockIdx.x;
    const float* x = (n < NSRC) ? xs + (long long)n * ORI : xt + (long long)(n - NSRC) * ORI;
    for (int c = threadIdx.x; c < K0PAD; c += 256) {
        float v = (c < 1024) ? x[c] : ((c < 1064) ? extra[n * 40 + c - 1024] : 0.f);
        bf16 h, l; bsplit(v, h, l);
        oh[(long long)n * K0PAD + c] = h;
        ol[(long long)n * K0PAD + c] = l;
    }
}
__global__ void k_xcatL(const bf16* __restrict__ fh, const bf16* __restrict__ fl,
                        const float* __restrict__ extra,
                        bf16* __restrict__ oh, bf16* __restrict__ ol, int l) {
    int n = blockIdx.x, c = threadIdx.x;   // 192 threads
    bf16 h = __float2bfloat16(0.f), lo = h;
    if (c < 128) {
        long long o = (long long)n * FINAL_IN + ORI + (l - 1) * EMBED + c;
        h = fh[o]; lo = fl[o];
    } else if (c < 168) {
        bsplit(extra[n * 40 + (c - 128)], h, lo);
    }
    oh[(long long)n * KLPAD + c] = h;
    ol[(long long)n * KLPAD + c] = lo;
}
__global__ void k_cat(const float* __restrict__ xin, const float* __restrict__ msg,
                      bf16* __restrict__ oh, bf16* __restrict__ ol) {
    int n = blockIdx.x, d = threadIdx.x;
    float v;
    if (d < EMBED) v = xin[n * EMBED + d];
    else           v = xin[n * EMBED + d - EMBED] - msg[n * EMBED + d - EMBED];
    bf16 h, l; bsplit(v, h, l);
    oh[(long long)n * CONV_IN + d] = h;
    ol[(long long)n * CONV_IN + d] = l;
}

// ----- stable CSR build (cnt layout: [chunk][dst], coalesced) -----
__global__ void k_count(const int* __restrict__ ei, int* __restrict__ cnt) {
    int e = blockIdx.x * 256 + threadIdx.x;
    int d = ei[NEDGE + e];
    atomicAdd(&cnt[(e >> 5) * 4096 + d], 1);
}
__global__ void k_colscan(int* __restrict__ cnt, int* __restrict__ tot) {
    int d = blockIdx.x * 256 + threadIdx.x;
    if (d >= 4096) return;
    int run = 0;
    for (int c = 0; c < NCHUNK; c++) {
        int v = cnt[c * 4096 + d];
        cnt[c * 4096 + d] = run;
        run += v;
    }
    tot[d] = run;
}
__global__ void k_scan(const int* __restrict__ tot, int* __restrict__ off) {
    __shared__ int s[1024];
    int tid = threadIdx.x;
    int v[4]; int sum = 0;
#pragma unroll
    for (int i = 0; i < 4; i++) { v[i] = tot[tid * 4 + i]; sum += v[i]; }
    s[tid] = sum; __syncthreads();
    for (int d = 1; d < 1024; d <<= 1) {
        int x = (tid >= d) ? s[tid - d] : 0;
        __syncthreads();
        s[tid] += x;
        __syncthreads();
    }
    int run = (tid == 0) ? 0 : s[tid - 1];
#pragma unroll
    for (int i = 0; i < 4; i++) { off[tid * 4 + i] = run; run += v[i]; }
    if (tid == 1023) off[4096] = run;
}
__global__ void k_place(const int* __restrict__ ei, const int* __restrict__ off,
                        int* __restrict__ cnt, int* __restrict__ eid) {
    int c = blockIdx.x * 256 + threadIdx.x;
    if (c >= NCHUNK) return;
    for (int j = 0; j < CHUNK; j++) {
        int e = c * CHUNK + j;
        int d = ei[NEDGE + e];
        int r = cnt[c * 4096 + d];
        cnt[c * 4096 + d] = r + 1;
        eid[off[d] + r] = e;
    }
}

// ----- spline gather + mean + root + tanh -> feat hi/lo -----
__global__ void k_spline_agg(const float* __restrict__ Y, const float* __restrict__ rootb,
                             const int* __restrict__ off, const int* __restrict__ eid,
                             const int* __restrict__ ei, const float* __restrict__ ea,
                             bf16* __restrict__ oh, bf16* __restrict__ ol) {
    int n = blockIdx.x, d = threadIdx.x;       // 128
    int beg = off[n], end = off[n + 1];

    auto contrib = [&](int e) -> float {
        int src = ei[e];
        float v0 = ea[e * 2] * 4.f, v1 = ea[e * 2 + 1] * 4.f;
        float l0 = floorf(v0), l1 = floorf(v1);
        float f0 = v0 - l0, f1 = v1 - l1;
        int i0 = (int)l0, i1 = (int)l1;
        const float* Ys = Y + (long long)src * YW;
        float r = 0.f;
#pragma unroll
        for (int s1 = 0; s1 < 2; s1++)
#pragma unroll
            for (int s0 = 0; s0 < 2; s0++) {
                int a0 = min(max(i0 + s0, 0), 4);
                int a1 = min(max(i1 + s1, 0), 4);
                float w = (s0 ? f0 : 1.f - f0) * (s1 ? f1 : 1.f - f1);
                r += w * Ys[(a0 + 5 * a1) * EMBED + d];
            }
        return r;
    };

    float acc0 = 0.f, acc1 = 0.f;
    int j = beg;
    for (; j + 2 <= end; j += 2) {
        acc0 += contrib(eid[j]);
        acc1 += contrib(eid[j + 1]);
    }
    if (j < end) acc0 += contrib(eid[j]);
    float acc = acc0 + acc1;

    float deg = (float)(end - beg);
    acc = acc / fmaxf(deg, 1.f);
    float v = tanhf(acc + rootb[n * EMBED + d]);
    bf16 h, l; bsplit(v, h, l);
    oh[(long long)n * FINAL_IN + d] = h;
    ol[(long long)n * FINAL_IN + d] = l;
}

__global__ void k_softmax(float* __restrict__ out) {
    int r = blockIdx.x;
    float* row = out + (long long)r * NT;
    __shared__ float sm[256];
    int tid = threadIdx.x;
    float a = row[tid], b = row[tid + 256];
    sm[tid] = fmaxf(a, b); __syncthreads();
    for (int s = 128; s > 0; s >>= 1) {
        if (tid < s) sm[tid] = fmaxf(sm[tid], sm[tid + s]);
        __syncthreads();
    }
    float mx = sm[0]; __syncthreads();
    float ea = expf(a - mx), eb = expf(b - mx);
    sm[tid] = ea + eb; __syncthreads();
    for (int s = 128; s > 0; s >>= 1) {
        if (tid < s) sm[tid] += sm[tid + s];
        __syncthreads();
    }
    float inv = 1.f / sm[0];
    row[tid] = ea * inv;
    row[tid + 256] = eb * inv;
}

// ---------------- host ----------------
#define GSMEM4 (2 * (2 * 128 * 80 + 20480))   // 81920
#define GSMEM2 (2 * (2 * 64 * 80 + 20480))    // 61440
#define GSMEM1 (2 * (2 * 32 * 80 + 20480))    // 51200

static void build_csr(const int* ei, int* off, int* eid, int* cnt, int* tot) {
    cudaMemsetAsync(cnt, 0, NCHUNK * 4096 * sizeof(int));
    k_count<<<NEDGE / 256, 256>>>(ei, cnt);
    k_colscan<<<16, 256>>>(cnt, tot);
    k_scan<<<1, 1024>>>(tot, off);
    k_place<<<4, 256>>>(ei, off, cnt, eid);
}

#define GETSYM(v, s) cudaGetSymbolAddress((void**)&v, s)

extern "C" void kernel_launch(void* const* d_in, const int* in_sizes, int n_in,
                              void* d_out, int out_size) {
    const float* t_in      = (const float*)d_in[0];
    const float* Xt        = (const float*)d_in[1];
    const float* x_s       = (const float*)d_in[2];
    const float* x_t       = (const float*)d_in[3];
    const float* ea_s      = (const float*)d_in[4];
    const float* ea_t      = (const float*)d_in[5];
    const float* lin0_w    = (const float*)d_in[6];
    const float* lin0_b    = (const float*)d_in[7];
    const float* lin_w     = (const float*)d_in[8];
    const float* lin_b     = (const float*)d_in[9];
    const float* conv_w    = (const float*)d_in[10];
    const float* conv_root = (const float*)d_in[11];
    const float* conv_bias = (const float*)d_in[12];
    const float* final_w   = (const float*)d_in[13];
    const float* final_b   = (const float*)d_in[14];
    const int*   ei_s      = (const int*)d_in[15];
    const int*   ei_t      = (const int*)d_in[16];
    float* out = (float*)d_out;

    cudaFuncSetAttribute(bgemm<4>, cudaFuncAttributeMaxDynamicSharedMemorySize, GSMEM4);
    cudaFuncSetAttribute(bgemm<2>, cudaFuncAttributeMaxDynamicSharedMemorySize, GSMEM2);
    cudaFuncSetAttribute(bgemm<1>, cudaFuncAttributeMaxDynamicSharedMemorySize, GSMEM1);

    bf16 *xcat_h, *xcat_l, *Xh, *Xl, *XTh, *XTl, *xinT_h, *xinT_l, *cat_h, *cat_l;
    bf16 *feat_h, *feat_l, *hh, *hl, *WrT_h, *WrT_l, *WT0_h, *WT0_l, *WTl_h, *WTl_l;
    bf16 *rtT_h, *rtT_l, *fwT_h, *fwT_l;
    float *xin, *msg, *rootb, *hf, *Y, *extra, *sums;
    int *cnt, *tot, *off_s, *eid_s, *off_t, *eid_t;
    GETSYM(xcat_h, g_xcat_h); GETSYM(xcat_l, g_xcat_l);
    GETSYM(Xh, g_Xh); GETSYM(Xl, g_Xl); GETSYM(XTh, g_XTh); GETSYM(XTl, g_XTl);
    GETSYM(xinT_h, g_xinT_h); GETSYM(xinT_l, g_xinT_l);
    GETSYM(cat_h, g_cat_h); GETSYM(cat_l, g_cat_l);
    GETSYM(feat_h, g_feat_h); GETSYM(feat_l, g_feat_l);
    GETSYM(hh, g_hh); GETSYM(hl, g_hl);
    GETSYM(WrT_h, g_WrT_h); GETSYM(WrT_l, g_WrT_l);
    GETSYM(WT0_h, g_WT0_h); GETSYM(WT0_l, g_WT0_l);
    GETSYM(WTl_h, g_WTl_h); GETSYM(WTl_l, g_WTl_l);
    GETSYM(rtT_h, g_rtT_h); GETSYM(rtT_l, g_rtT_l);
    GETSYM(fwT_h, g_fwT_h); GETSYM(fwT_l, g_fwT_l);
    GETSYM(xin, g_xin); GETSYM(msg, g_msg); GETSYM(rootb, g_rootb);
    GETSYM(hf, g_hf); GETSYM(Y, g_Y); GETSYM(extra, g_extra); GETSYM(sums, g_sum);
    GETSYM(cnt, g_cnt); GETSYM(tot, g_tot);
    GETSYM(off_s, g_off_s); GETSYM(eid_s, g_eid_s);
    GETSYM(off_t, g_off_t); GETSYM(eid_t, g_eid_t);

    dim3 tb(32, 8);

    // ---- prep ----
    k_rowsum<<<NSRC, 256>>>(Xt, sums);
    k_colsum<<<BATCH, 512>>>(Xt, sums + NSRC);
    k_extra<<<32, 256>>>(sums, t_in, extra);
    k_xcat0<<<NTOT, 256>>>(x_s, x_t, extra, xcat_h, xcat_l);
    k_convT<<<dim3(4, K0PAD / 32, 1), tb>>>(lin0_w, 1064, EMBED, EMBED, 0,
                                            WT0_h, WT0_l, K0PAD, 0);
    // xin(l=0) = xcat @ W0 + b
    bgemm<1><<<dim3(1, NTOT / 32, 1), 256, GSMEM1>>>(
        xcat_h, xcat_l, K0PAD, 0, WT0_h, WT0_l, K0PAD, 0,
        xin, EMBED, 0, lin0_b, K0PAD);

    k_convS<<<(BATCH * NS * NT + 255) / 256, 256>>>(Xt, Xh, Xl, BATCH * NS * NT);
    k_convT<<<dim3(16, 16, BATCH), tb>>>(Xt, NS, NT, NT, (long long)NS * NT,
                                         XTh, XTl, NS, (long long)NS * NT);
    k_convT<<<dim3(4, KLPAD / 32, 2), tb>>>(lin_w, 168, EMBED, EMBED, 168 * EMBED,
                                            WTl_h, WTl_l, KLPAD, (long long)EMBED * KLPAD);
    k_convT<<<dim3(4, 8, 75), tb>>>(conv_w, CONV_IN, EMBED, EMBED, (long long)CONV_IN * EMBED,
                                    WrT_h, WrT_l, CONV_IN, (long long)EMBED * CONV_IN);
    k_convT<<<dim3(4, 8, 3), tb>>>(conv_root, CONV_IN, EMBED, EMBED, (long long)CONV_IN * EMBED,
                                   rtT_h, rtT_l, CONV_IN, (long long)EMBED * CONV_IN);
    k_convT<<<dim3(4, FINAL_IN / 32, 1), tb>>>(final_w, FINAL_IN, EMBED, EMBED, 0,
                                               fwT_h, fwT_l, FINAL_IN, 0);
    k_copyx<<<NTOT, 256>>>(x_s, x_t, feat_h, feat_l);
    build_csr(ei_s, off_s, eid_s, cnt, tot);
    build_csr(ei_t, off_t, eid_t, cnt, tot);

    for (int l = 0; l < 3; l++) {
        if (l > 0) {
            k_xcatL<<<NTOT, 192>>>(feat_h, feat_l, extra, xcat_h, xcat_l, l);
            const bf16* wh = WTl_h + (long long)(l - 1) * EMBED * KLPAD;
            const bf16* wl = WTl_l + (long long)(l - 1) * EMBED * KLPAD;
            bgemm<1><<<dim3(1, NTOT / 32, 1), 256, GSMEM1>>>(
                xcat_h, xcat_l, KLPAD, 0, wh, wl, KLPAD, 0,
                xin, EMBED, 0, lin_b + (l - 1) * EMBED, KLPAD);
        }
        // xinT (fp32 -> transposed split)
        k_convT<<<dim3(4, 256, 1), tb>>>(xin, NTOT, EMBED, EMBED, 0,
                                         xinT_h, xinT_l, NTOT, 0);
        // tgt_msg: A = Xt[b], B = xinT target cols
        bgemm<1><<<dim3(1, NS / 32, 8), 256, GSMEM1>>>(
            Xh, Xl, NT, (long long)NS * NT,
            xinT_h + NSRC, xinT_l + NSRC, NTOT, NS,
            msg, EMBED, (long long)NS * EMBED, nullptr, NT);
        // src_msg: A = Xt[b]^T, B = xinT source cols
        bgemm<1><<<dim3(1, NT / 32, 8), 256, GSMEM1>>>(
            XTh, XTl, NS, (long long)NS * NT,
            xinT_h, xinT_l, NTOT, NS,
            msg + (long long)NSRC * EMBED, EMBED, (long long)NT * EMBED, nullptr, NS);

        k_cat<<<NTOT, 256>>>(xin, msg, cat_h, cat_l);

        // Y = cat @ Wr[l]
        bgemm<4><<<dim3(YW / 128, NTOT / 128, 1), 256, GSMEM4>>>(
            cat_h, cat_l, CONV_IN, 0,
            WrT_h + (long long)l * YW * CONV_IN, WrT_l + (long long)l * YW * CONV_IN, CONV_IN, 0,
            Y, YW, 0, nullptr, CONV_IN);
        // rootb = cat @ root + bias
        bgemm<1><<<dim3(1, NTOT / 32, 1), 256, GSMEM1>>>(
            cat_h, cat_l, CONV_IN, 0,
            rtT_h + (long long)l * EMBED * CONV_IN, rtT_l + (long long)l * EMBED * CONV_IN, CONV_IN, 0,
            rootb, EMBED, 0, conv_bias + l * EMBED, CONV_IN);

        k_spline_agg<<<NSRC, 128>>>(Y, rootb, off_s, eid_s, ei_s, ea_s,
                                    feat_h + ORI + l * EMBED, feat_l + ORI + l * EMBED);
        k_spline_agg<<<NSRC, 128>>>(Y + (long long)NSRC * YW, rootb + (long long)NSRC * EMBED,
                                    off_t, eid_t, ei_t, ea_t,
                                    feat_h + (long long)NSRC * FINAL_IN + ORI + l * EMBED,
                                    feat_l + (long long)NSRC * FINAL_IN + ORI + l * EMBED);
    }

    // h = feat @ final_w + final_b
    bgemm<1><<<dim3(1, NTOT / 32, 1), 256, GSMEM1>>>(
        feat_h, feat_l, FINAL_IN, 0, fwT_h, fwT_l, FINAL_IN, 0,
        hf, EMBED, 0, final_b, FINAL_IN);
    k_convS<<<(NTOT * EMBED + 255) / 256, 256>>>(hf, hh, hl, NTOT * EMBED);

    // sim = h_s @ h_t^T per batch
    bgemm<2><<<dim3(4, 8, 8), 256, GSMEM2>>>(
        hh, hl, EMBED, (long long)NS * EMBED,
        hh + (long long)NSRC * EMBED, hl + (long long)NSRC * EMBED, EMBED, (long long)NT * EMBED,
        out, NT, (long long)NS * NT, nullptr, EMBED);

    k_softmax<<<NSRC, 256>>>(out);
}